// round 12
// baseline (speedup 1.0000x reference)
#include <cuda_runtime.h>
#include <cuda_fp16.h>
#include <cstdint>
#include <math.h>

// ---------------- Problem constants ----------------
#define D_MODEL   1024
#define HEADDIM   64
#define D_STATE   128
#define D_INNER   2048
#define NHEADS    32
#define CONV_DIM  2304           // D_INNER + 2*D_STATE
#define D_IN_PROJ 4384           // 2*D_INNER + 2*D_STATE + NHEADS
#define N_MAIN    4352           // D_IN_PROJ - NHEADS (cols via fp16 GEMM)
#define BATCH     4
#define SEQ       2048
#define ROWS      (BATCH*SEQ)    // 8192
#define EPSV      1e-5f

#define NCHUNK    16
#define LCH       128
#define NBH       (BATCH*NHEADS) // 128
#define STATE_SZ  (HEADDIM*D_STATE)  // 8192

#define PR  132                  // padded 128-float row
#define PX  68                   // padded 64-float row

typedef unsigned long long ull;

// ---------------- Scratch ----------------
__device__ float g_zxb[(size_t)ROWS * D_IN_PROJ];
__device__ float g_xbc[(size_t)ROWS * CONV_DIM];
__device__ float g_dtraw[(size_t)ROWS * NHEADS];    // exact fp32 dt projection
__device__ float g_dt [NBH*SEQ];
__device__ float g_la [NBH*SEQ];                    // A*dt (log dA)
__device__ float g_yb [(size_t)ROWS * D_INNER];

__device__ float g_st  [(size_t)NBH * NCHUNK * STATE_SZ];
__device__ float g_hini[(size_t)NBH * NCHUNK * STATE_SZ];
__device__ float g_cum [NBH * NCHUNK];

// fp16 split operands for tensor-core GEMMs
__device__ __half g_qh [(size_t)ROWS * D_MODEL];
__device__ __half g_ql [(size_t)ROWS * D_MODEL];
__device__ __half g_w1h[(size_t)N_MAIN * D_MODEL];
__device__ __half g_w1l[(size_t)N_MAIN * D_MODEL];
__device__ __half g_ynh[(size_t)ROWS * D_INNER];
__device__ __half g_ynl[(size_t)ROWS * D_INNER];
__device__ __half g_w2h[(size_t)D_MODEL * D_INNER];
__device__ __half g_w2l[(size_t)D_MODEL * D_INNER];

// ---------------- f32x2 packed helpers ----------------
__device__ __forceinline__ ull pack2(float lo, float hi) {
    ull r; asm("mov.b64 %0, {%1,%2};" : "=l"(r) : "f"(lo), "f"(hi)); return r;
}
__device__ __forceinline__ void unpack2(ull v, float& lo, float& hi) {
    asm("mov.b64 {%0,%1}, %2;" : "=f"(lo), "=f"(hi) : "l"(v));
}
__device__ __forceinline__ void fma2(ull& d, ull a, ull b) {
    asm("fma.rn.f32x2 %0, %1, %2, %0;" : "+l"(d) : "l"(a), "l"(b));
}
__device__ __forceinline__ ull mul2(ull a, ull b) {
    ull r; asm("mul.rn.f32x2 %0, %1, %2;" : "=l"(r) : "l"(a), "l"(b)); return r;
}
#define COMP(v,k) ((k)==0?(v).x:((k)==1?(v).y:((k)==2?(v).z:(v).w)))

// ---------------- cp.async helpers ----------------
__device__ __forceinline__ void cp16(unsigned s, const void* g) {
    asm volatile("cp.async.ca.shared.global [%0], [%1], 16;" :: "r"(s), "l"(g));
}
__device__ __forceinline__ void cp_commit() { asm volatile("cp.async.commit_group;"); }
template<int N> __device__ __forceinline__ void cp_wait() {
    asm volatile("cp.async.wait_group %0;" :: "n"(N));
}
__device__ __forceinline__ unsigned smem_u32(const void* p) {
    return (unsigned)__cvta_generic_to_shared(p);
}

// ---------------- mma.sync + ldmatrix (fp16) ----------------
#define LDSM4(r, addr) \
    asm volatile("ldmatrix.sync.aligned.m8n8.x4.shared.b16 {%0,%1,%2,%3}, [%4];" \
        : "=r"((r)[0]), "=r"((r)[1]), "=r"((r)[2]), "=r"((r)[3]) : "r"(addr))

#define MMA16816H(d, a, b) \
    asm volatile("mma.sync.aligned.m16n8k16.row.col.f32.f16.f16.f32 " \
        "{%0,%1,%2,%3}, {%4,%5,%6,%7}, {%8,%9}, {%0,%1,%2,%3};" \
        : "+f"((d)[0]), "+f"((d)[1]), "+f"((d)[2]), "+f"((d)[3]) \
        : "r"((a)[0]), "r"((a)[1]), "r"((a)[2]), "r"((a)[3]), \
          "r"((b)[0]), "r"((b)[1]))

// =====================================================================
// Split-fp16 HMMA GEMM (NT): C = Ah*Bh + Al*Bh   (fp32 accum)
// A's fp16 residual captured; B carries a single 2^-11-class rounding.
// CTA tile 128(M) x 256(N), BK=64, 3-stage cp.async pipeline.
// Stage layout (64KB): Ah@0 16K | Al@16K | Bh@32K 32K
// =====================================================================
#define GEMM_STG   65536
#define GEMM_SMEM  (3*GEMM_STG)

__global__ void __launch_bounds__(256, 1)
gemm_mma(const __half* __restrict__ A_h, const __half* __restrict__ A_l,
         const __half* __restrict__ B_h,
         float* __restrict__ C, int M, int N, int K, int ldC)
{
    extern __shared__ __align__(1024) char sm[];
    const unsigned base = smem_u32(sm);
    const int tid  = threadIdx.x;
    const int lane = tid & 31;
    const int wid  = tid >> 5;
    const int wm   = wid >> 2;
    const int wn   = wid & 3;
    const int m0   = blockIdx.y * 128;
    const int n0   = blockIdx.x * 256;

    float acc[4][8][4];
#pragma unroll
    for (int t = 0; t < 4; t++)
#pragma unroll
        for (int u = 0; u < 8; u++)
#pragma unroll
            for (int v = 0; v < 4; v++) acc[t][u][v] = 0.f;

    auto load_stage = [&](int s, unsigned stg) {
        const int k0 = s * 64;
        // A hi/lo: 128 rows x 8 chunks of 16B -> 4/thread/matrix
#pragma unroll
        for (int i = 0; i < 4; i++) {
            const int ch = tid + i * 256;
            const int row = ch >> 3, c = ch & 7;
            const unsigned off = (unsigned)(row * 128) + ((unsigned)(c ^ (row & 7)) << 4);
            const size_t g = (size_t)(m0 + row) * K + k0 + c * 8;
            cp16(stg + off,         A_h + g);
            cp16(stg + 16384 + off, A_l + g);
        }
        // B hi: 256 rows x 8 chunks -> 8/thread
#pragma unroll
        for (int i = 0; i < 8; i++) {
            const int ch = tid + i * 256;
            const int row = ch >> 3, c = ch & 7;
            const unsigned off = (unsigned)(row * 128) + ((unsigned)(c ^ (row & 7)) << 4);
            const size_t g = (size_t)(n0 + row) * K + k0 + c * 8;
            cp16(stg + 32768 + off, B_h + g);
        }
        cp_commit();
    };

    const int S = K / 64;
    load_stage(0, base);
    if (S > 1) load_stage(1, base + GEMM_STG);

    for (int s = 0; s < S; s++) {
        const unsigned stg = base + (unsigned)(s % 3) * GEMM_STG;
        if (s + 2 < S) { load_stage(s + 2, base + (unsigned)((s + 2) % 3) * GEMM_STG); cp_wait<2>(); }
        else if (s + 1 < S) { cp_wait<1>(); }
        else { cp_wait<0>(); }
        __syncthreads();

        const unsigned stgA  = stg;
        const unsigned stgAl = stg + 16384;
        const unsigned stgB  = stg + 32768;

#pragma unroll
        for (int ks = 0; ks < 4; ks++) {
            unsigned ah[4][4], al[4][4], bb[8][2];
            const unsigned akoff = ((unsigned)((ks * 2 + (lane >> 4)) ^ (lane & 7))) << 4;
#pragma unroll
            for (int t = 0; t < 4; t++) {
                const unsigned ro = (unsigned)((wm * 64 + t * 16 + (lane & 15)) * 128);
                LDSM4(ah[t], stgA  + ro + akoff);
                LDSM4(al[t], stgAl + ro + akoff);
            }
            const unsigned bkoff = ((unsigned)((ks * 2 + ((lane >> 3) & 1)) ^ (lane & 7))) << 4;
#pragma unroll
            for (int p = 0; p < 4; p++) {
                const unsigned ro = (unsigned)((wn * 64 + p * 16 + (lane & 7) + ((lane & 16) >> 1)) * 128);
                unsigned r[4];
                LDSM4(r, stgB + ro + bkoff);
                bb[2*p][0] = r[0]; bb[2*p][1] = r[1];
                bb[2*p+1][0] = r[2]; bb[2*p+1][1] = r[3];
            }
#pragma unroll
            for (int t = 0; t < 4; t++)
#pragma unroll
                for (int u = 0; u < 8; u++) {
                    MMA16816H(acc[t][u], ah[t], bb[u]);
                    MMA16816H(acc[t][u], al[t], bb[u]);
                }
        }
        __syncthreads();
    }

#pragma unroll
    for (int t = 0; t < 4; t++) {
        const int row = m0 + wm * 64 + t * 16 + (lane >> 2);
#pragma unroll
        for (int u = 0; u < 8; u++) {
            const int col = n0 + wn * 64 + u * 8 + (lane & 3) * 2;
            if (col < N) {
                *(float2*)(C + (size_t)row * ldC + col)       = make_float2(acc[t][u][0], acc[t][u][1]);
                *(float2*)(C + (size_t)(row + 8) * ldC + col) = make_float2(acc[t][u][2], acc[t][u][3]);
            }
        }
    }
}

// =====================================================================
// fp32 -> (fp16 hi, fp16 lo) split conversion
// =====================================================================
__global__ void __launch_bounds__(256) cvt_pair(const float* __restrict__ src,
                                                __half* __restrict__ h,
                                                __half* __restrict__ l, int n4)
{
    const int i = blockIdx.x * 256 + threadIdx.x;
    if (i >= n4) return;
    const float4 v = ((const float4*)src)[i];
    __half h0 = __float2half_rn(v.x), h1 = __float2half_rn(v.y),
           h2 = __float2half_rn(v.z), h3 = __float2half_rn(v.w);
    __half l0 = __float2half_rn(v.x - __half2float(h0));
    __half l1 = __float2half_rn(v.y - __half2float(h1));
    __half l2 = __float2half_rn(v.z - __half2float(h2));
    __half l3 = __float2half_rn(v.w - __half2float(h3));
    ushort4 hv = make_ushort4(__half_as_ushort(h0), __half_as_ushort(h1),
                              __half_as_ushort(h2), __half_as_ushort(h3));
    ushort4 lv = make_ushort4(__half_as_ushort(l0), __half_as_ushort(l1),
                              __half_as_ushort(l2), __half_as_ushort(l3));
    ((ushort4*)h)[i] = hv;
    ((ushort4*)l)[i] = lv;
}

// =====================================================================
// Exact fp32 dt projection: dtraw[r][c] = q[r] . w1[4352+c]  (c < 32)
// one warp per row; lane = output column.
// =====================================================================
__global__ void __launch_bounds__(256) dtproj_kernel(const float* __restrict__ q,
                                                     const float* __restrict__ w1)
{
    const int wid  = threadIdx.x >> 5;
    const int lane = threadIdx.x & 31;
    const int row  = blockIdx.x * 8 + wid;
    const float* qr = q + (size_t)row * D_MODEL;
    const float* wr = w1 + ((size_t)N_MAIN + lane) * D_MODEL;
    float acc = 0.f;
    for (int k0 = 0; k0 < D_MODEL; k0 += 32) {
        const float qv = qr[k0 + lane];
#pragma unroll
        for (int j = 0; j < 32; j++) {
            const float qb = __shfl_sync(0xffffffffu, qv, j);
            acc += qb * wr[k0 + j];
        }
    }
    g_dtraw[(size_t)row * NHEADS + lane] = acc;
}

// =====================================================================
// Depthwise causal conv (width 4) + SiLU
// =====================================================================
__global__ void __launch_bounds__(256) conv_silu_kernel(const float* __restrict__ conv_w,
                                                        const float* __restrict__ conv_b)
{
    const int c  = blockIdx.x * 256 + threadIdx.x;
    const int l0 = blockIdx.y * 128;
    const int b  = blockIdx.z;

    const float w0 = conv_w[c*4+0], w1 = conv_w[c*4+1],
                w2 = conv_w[c*4+2], w3 = conv_w[c*4+3];
    const float bias = conv_b[c];

    const float* src = g_zxb + (size_t)(b*SEQ) * D_IN_PROJ + D_INNER + c;
    float*       dst = g_xbc + (size_t)(b*SEQ) * CONV_DIM + c;

    float xm3 = (l0-3 >= 0) ? src[(size_t)(l0-3) * D_IN_PROJ] : 0.f;
    float xm2 = (l0-2 >= 0) ? src[(size_t)(l0-2) * D_IN_PROJ] : 0.f;
    float xm1 = (l0-1 >= 0) ? src[(size_t)(l0-1) * D_IN_PROJ] : 0.f;

    for (int l = l0; l < l0 + 128; l++) {
        const float xc = src[(size_t)l * D_IN_PROJ];
        float v = bias + w0*xm3 + w1*xm2 + w2*xm1 + w3*xc;
        v = v / (1.f + expf(-v));
        dst[(size_t)l * CONV_DIM] = v;
        xm3 = xm2; xm2 = xm1; xm1 = xc;
    }
}

// =====================================================================
// dt = softplus(dtraw + dt_bias); la = A*dt   layout [bh][l]
// =====================================================================
__global__ void __launch_bounds__(256) dt_kernel(const float* __restrict__ dt_bias,
                                                 const float* __restrict__ A_log)
{
    const int idx = blockIdx.x * 256 + threadIdx.x;
    if (idx >= NBH*SEQ) return;
    const int l = idx & (SEQ-1);
    const int h = (idx >> 11) & (NHEADS-1);
    const int b = idx >> 16;
    const float raw = g_dtraw[(size_t)(b*SEQ + l) * NHEADS + h] + dt_bias[h];
    const float sp = (raw > 20.f) ? raw : log1pf(expf(raw));
    const float Ahv = -expf(A_log[h]);
    g_dt[idx] = sp;
    g_la[idx] = Ahv * sp;
}

// =====================================================================
// SSD phase 1: per-chunk final local state via outer-product GEMM.
// =====================================================================
#define SSDA_SMEM ((128*PR + 128*PX + 384) * 4)

__global__ void __launch_bounds__(256, 2) ssd_state_kernel()
{
    extern __shared__ float sma[];
    float* sB  = sma;                 // [128][PR]
    float* sVW = sB + 128*PR;         // [128][PX]  dt*w*x
    float* sCS = sVW + 128*PX;        // [128]
    float* sDT = sCS + 128;           // [128]
    float* sLA = sDT + 128;           // [128]

    const int ck = blockIdx.x, bh = blockIdx.y;
    const int b  = bh >> 5, hh = bh & 31;
    const int tid = threadIdx.x;
    const size_t rbase = (size_t)(b*SEQ + ck*LCH);

#pragma unroll
    for (int i = 0; i < 16; i++) {
        int idx = i*256 + tid; int t = idx >> 5, f4 = idx & 31;
        cp16(smem_u32(sB + t*PR + f4*4),
             g_xbc + (rbase + t)*CONV_DIM + D_INNER + f4*4);
    }
#pragma unroll
    for (int i = 0; i < 8; i++) {
        int idx = i*256 + tid; int t = idx >> 4, f4 = idx & 15;
        cp16(smem_u32(sVW + t*PX + f4*4),
             g_xbc + (rbase + t)*CONV_DIM + hh*HEADDIM + f4*4);
    }
    if (tid < 128) {
        sDT[tid] = g_dt[(size_t)bh*SEQ + ck*LCH + tid];
        sLA[tid] = g_la[(size_t)bh*SEQ + ck*LCH + tid];
    }
    cp_commit(); cp_wait<0>();
    __syncthreads();
    if (tid == 0) {
        float c = 0.f;
        for (int s = 0; s < 128; s++) { c += sLA[s]; sCS[s] = c; }
    }
    __syncthreads();
    const float csL = sCS[127];
    if (tid < 128) {
        const float w = __expf(csL - sCS[tid]) * sDT[tid];
        float* row = sVW + tid*PX;
#pragma unroll
        for (int p = 0; p < 64; p += 4) {
            float4 v = *(float4*)(row + p);
            v.x *= w; v.y *= w; v.z *= w; v.w *= w;
            *(float4*)(row + p) = v;
        }
    }
    if (tid == 0) g_cum[bh*NCHUNK + ck] = __expf(csL);
    __syncthreads();

    const int pg = tid >> 4;
    const int ng = tid & 15;

    ull Sp[4][4];
#pragma unroll
    for (int i = 0; i < 4; i++)
#pragma unroll
        for (int q = 0; q < 4; q++) Sp[i][q] = 0ull;

#pragma unroll 4
    for (int s = 0; s < 128; s++) {
        const float4 v4  = *(const float4*)(sVW + s*PX + pg*4);
        const float4 b40 = *(const float4*)(sB + s*PR + ng*8);
        const float4 b41 = *(const float4*)(sB + s*PR + ng*8 + 4);
        ull bp[4] = { pack2(b40.x, b40.y), pack2(b40.z, b40.w),
                      pack2(b41.x, b41.y), pack2(b41.z, b41.w) };
#pragma unroll
        for (int i = 0; i < 4; i++) {
            const float vv = COMP(v4, i);
            const ull vc = pack2(vv, vv);
#pragma unroll
            for (int q = 0; q < 4; q++) fma2(Sp[i][q], vc, bp[q]);
        }
    }

    float* dst = g_st + (size_t)(bh*NCHUNK + ck)*STATE_SZ;
#pragma unroll
    for (int i = 0; i < 4; i++) {
        const int p = pg*4 + i;
        float o[8];
#pragma unroll
        for (int q = 0; q < 4; q++) unpack2(Sp[i][q], o[q*2], o[q*2+1]);
        *(float4*)(dst + p*D_STATE + ng*8)     = make_float4(o[0], o[1], o[2], o[3]);
        *(float4*)(dst + p*D_STATE + ng*8 + 4) = make_float4(o[4], o[5], o[6], o[7]);
    }
}

// =====================================================================
// SSD phase 2: combine across chunks.
// =====================================================================
__global__ void __launch_bounds__(256) chunk_combine_kernel()
{
    const int bh  = blockIdx.x;
    const int tid = threadIdx.x;
    const size_t off = tid * 32;

    float4 h[8];
#pragma unroll
    for (int i = 0; i < 8; i++) h[i] = make_float4(0.f, 0.f, 0.f, 0.f);

    for (int ck = 0; ck < NCHUNK; ck++) {
        float4* hi = (float4*)(g_hini + (size_t)(bh * NCHUNK + ck) * STATE_SZ + off);
#pragma unroll
        for (int i = 0; i < 8; i++) hi[i] = h[i];
        if (ck < NCHUNK - 1) {
            const float a = g_cum[bh * NCHUNK + ck];
            const float4* s = (const float4*)(g_st + (size_t)(bh * NCHUNK + ck) * STATE_SZ + off);
#pragma unroll
            for (int i = 0; i < 8; i++) {
                float4 sv = s[i];
                h[i].x = a * h[i].x + sv.x;
                h[i].y = a * h[i].y + sv.y;
                h[i].z = a * h[i].z + sv.z;
                h[i].w = a * h[i].w + sv.w;
            }
        }
    }
}

// =====================================================================
// SSD phase 3: per-chunk outputs via GEMMs.
// =====================================================================
#define SSDO_SMEM ((2*128*PR + 128*PX + 64*PR + 384) * 4)

__global__ void __launch_bounds__(256, 1) ssd_out_kernel(const float* __restrict__ Dvec)
{
    extern __shared__ float smo[];
    float* sC  = smo;                  // [128][PR]  (reused as sXT [64][PR])
    float* sB  = sC + 128*PR;          // [128][PR]  (reused as M)
    float* sX  = sB + 128*PR;          // [128][PX]
    float* sH  = sX + 128*PX;          // [64][PR]
    float* sCS = sH + 64*PR;           // [128]
    float* sDT = sCS + 128;            // [128]
    float* sLA = sDT + 128;            // [128]
    float* sXT = sC;

    const int ck = blockIdx.x, bh = blockIdx.y;
    const int b  = bh >> 5, hh = bh & 31;
    const int tid = threadIdx.x;
    const size_t rbase = (size_t)(b*SEQ + ck*LCH);

#pragma unroll
    for (int i = 0; i < 16; i++) {
        int idx = i*256 + tid; int t = idx >> 5, f4 = idx & 31;
        const float* row = g_xbc + (rbase + t)*CONV_DIM;
        cp16(smem_u32(sC + t*PR + f4*4), row + D_INNER + D_STATE + f4*4);
        cp16(smem_u32(sB + t*PR + f4*4), row + D_INNER + f4*4);
    }
#pragma unroll
    for (int i = 0; i < 8; i++) {
        int idx = i*256 + tid; int t = idx >> 4, f4 = idx & 15;
        cp16(smem_u32(sX + t*PX + f4*4),
             g_xbc + (rbase + t)*CONV_DIM + hh*HEADDIM + f4*4);
    }
    {
        const float* hsrc = g_hini + (size_t)(bh*NCHUNK + ck)*STATE_SZ;
#pragma unroll
        for (int i = 0; i < 8; i++) {
            int idx = i*256 + tid; int p = idx >> 5, f4 = idx & 31;
            cp16(smem_u32(sH + p*PR + f4*4), hsrc + p*D_STATE + f4*4);
        }
    }
    if (tid < 128) {
        sDT[tid] = g_dt[(size_t)bh*SEQ + ck*LCH + tid];
        sLA[tid] = g_la[(size_t)bh*SEQ + ck*LCH + tid];
    }
    cp_commit(); cp_wait<0>();
    __syncthreads();
    if (tid == 0) {
        float c = 0.f;
        for (int s = 0; s < 128; s++) { c += sLA[s]; sCS[s] = c; }
    }
    __syncthreads();

    const int tt = tid >> 4;
    const int tp = tid & 15;

    ull Yp[8][2];
#pragma unroll
    for (int i = 0; i < 8; i++) { Yp[i][0] = 0ull; Yp[i][1] = 0ull; }
    ull Gp[8][4];
#pragma unroll
    for (int i = 0; i < 8; i++)
#pragma unroll
        for (int q = 0; q < 4; q++) Gp[i][q] = 0ull;

    for (int n4 = 0; n4 < 32; n4++) {
        float4 c4[8], h4[4], b4[8];
#pragma unroll
        for (int i = 0; i < 8; i++) c4[i] = *(const float4*)(sC + (tt*8+i)*PR + n4*4);
#pragma unroll
        for (int j = 0; j < 4; j++) h4[j] = *(const float4*)(sH + (tp+16*j)*PR + n4*4);
#pragma unroll
        for (int m = 0; m < 8; m++) b4[m] = *(const float4*)(sB + (tp+16*m)*PR + n4*4);
#pragma unroll
        for (int k = 0; k < 4; k++) {
            ull hq[2] = { pack2(COMP(h4[0],k), COMP(h4[1],k)),
                          pack2(COMP(h4[2],k), COMP(h4[3],k)) };
            ull bq[4];
#pragma unroll
            for (int q = 0; q < 4; q++)
                bq[q] = pack2(COMP(b4[2*q],k), COMP(b4[2*q+1],k));
#pragma unroll
            for (int i = 0; i < 8; i++) {
                const float cv = COMP(c4[i], k);
                const ull cc = pack2(cv, cv);
                fma2(Yp[i][0], cc, hq[0]);
                fma2(Yp[i][1], cc, hq[1]);
#pragma unroll
                for (int q = 0; q < 4; q++) fma2(Gp[i][q], cc, bq[q]);
            }
        }
    }

#pragma unroll
    for (int i = 0; i < 8; i++) {
        const float w = __expf(sCS[tt*8 + i]);
        const ull ww = pack2(w, w);
        Yp[i][0] = mul2(Yp[i][0], ww);
        Yp[i][1] = mul2(Yp[i][1], ww);
    }

    __syncthreads();

#pragma unroll
    for (int i = 0; i < 8; i++) {
        const int t = tt*8 + i;
        const float et = sCS[t];
#pragma unroll
        for (int q = 0; q < 4; q++) {
            float g0, g1; unpack2(Gp[i][q], g0, g1);
            const int s0 = tp + 16*(2*q);
            const int s1 = tp + 16*(2*q + 1);
            sB[t*PR + s0] = (s0 <= t) ? g0 * __expf(et - sCS[s0]) * sDT[s0] : 0.f;
            sB[t*PR + s1] = (s1 <= t) ? g1 * __expf(et - sCS[s1]) * sDT[s1] : 0.f;
        }
    }
#pragma unroll
    for (int i = 0; i < 32; i++) {
        int e = i*256 + tid; int s = e >> 6, p = e & 63;
        sXT[p*PR + s] = sX[s*PX + p];
    }
    __syncthreads();

    for (int s4 = 0; s4 < 32; s4++) {
        float4 m4[8], x4[4];
#pragma unroll
        for (int i = 0; i < 8; i++) m4[i] = *(const float4*)(sB + (tt*8+i)*PR + s4*4);
#pragma unroll
        for (int j = 0; j < 4; j++) x4[j] = *(const float4*)(sXT + (tp+16*j)*PR + s4*4);
#pragma unroll
        for (int k = 0; k < 4; k++) {
            ull xq[2] = { pack2(COMP(x4[0],k), COMP(x4[1],k)),
                          pack2(COMP(x4[2],k), COMP(x4[3],k)) };
#pragma unroll
            for (int i = 0; i < 8; i++) {
                const float mv = COMP(m4[i], k);
                const ull mm = pack2(mv, mv);
                fma2(Yp[i][0], mm, xq[0]);
                fma2(Yp[i][1], mm, xq[1]);
            }
        }
    }

    const float Dv = Dvec[hh];
#pragma unroll
    for (int i = 0; i < 8; i++) {
        const int t = tt*8 + i;
        float* orow = g_yb + ((rbase + t) * NHEADS + hh) * HEADDIM;
        float y0, y1, y2, y3;
        unpack2(Yp[i][0], y0, y1);
        unpack2(Yp[i][1], y2, y3);
        orow[tp]      = y0 + Dv * sX[t*PX + tp];
        orow[tp + 16] = y1 + Dv * sX[t*PX + tp + 16];
        orow[tp + 32] = y2 + Dv * sX[t*PX + tp + 32];
        orow[tp + 48] = y3 + Dv * sX[t*PX + tp + 48];
    }
}

// =====================================================================
// y = yb * silu(z); rmsnorm; write fp16 hi/lo split (GEMM2 A operand)
// =====================================================================
__global__ void __launch_bounds__(256) gate_norm_kernel(const float* __restrict__ norm_w)
{
    const int row = blockIdx.x;
    const int tid = threadIdx.x;
    const float* yb = g_yb + (size_t)row * D_INNER;
    const float* zr = g_zxb + (size_t)row * D_IN_PROJ;

    float4 v[2];
    float ss = 0.f;
#pragma unroll
    for (int j = 0; j < 2; j++) {
        const int idx = tid + j*256;        // float4 index
        const float4 z4 = ((const float4*)zr)[idx];
        const float4 y4 = ((const float4*)yb)[idx];
        float4 val;
        val.x = y4.x * (z4.x / (1.f + expf(-z4.x)));
        val.y = y4.y * (z4.y / (1.f + expf(-z4.y)));
        val.z = y4.z * (z4.z / (1.f + expf(-z4.z)));
        val.w = y4.w * (z4.w / (1.f + expf(-z4.w)));
        v[j] = val;
        ss += val.x*val.x + val.y*val.y + val.z*val.z + val.w*val.w;
    }
#pragma unroll
    for (int o = 16; o > 0; o >>= 1) ss += __shfl_xor_sync(0xffffffffu, ss, o);

    __shared__ float red[8];
    __shared__ float sscale;
    if ((tid & 31) == 0) red[tid >> 5] = ss;
    __syncthreads();
    if (tid == 0) {
        float tot = 0.f;
#pragma unroll
        for (int i = 0; i < 8; i++) tot += red[i];
        sscale = rsqrtf(tot / (float)D_INNER + EPSV);
    }
    __syncthreads();
    const float scale = sscale;

    __half* oh = g_ynh + (size_t)row * D_INNER;
    __half* ol = g_ynl + (size_t)row * D_INNER;
#pragma unroll
    for (int j = 0; j < 2; j++) {
        const int idx = tid + j*256;
        const float4 w4 = ((const float4*)norm_w)[idx];
        float y[4] = { v[j].x * scale * w4.x, v[j].y * scale * w4.y,
                       v[j].z * scale * w4.z, v[j].w * scale * w4.w };
        ushort4 hv, lv;
        __half h0 = __float2half_rn(y[0]); hv.x = __half_as_ushort(h0);
        __half h1 = __float2half_rn(y[1]); hv.y = __half_as_ushort(h1);
        __half h2 = __float2half_rn(y[2]); hv.z = __half_as_ushort(h2);
        __half h3 = __float2half_rn(y[3]); hv.w = __half_as_ushort(h3);
        lv.x = __half_as_ushort(__float2half_rn(y[0] - __half2float(h0)));
        lv.y = __half_as_ushort(__float2half_rn(y[1] - __half2float(h1)));
        lv.z = __half_as_ushort(__float2half_rn(y[2] - __half2float(h2)));
        lv.w = __half_as_ushort(__float2half_rn(y[3] - __half2float(h3)));
        ((ushort4*)oh)[idx] = hv;
        ((ushort4*)ol)[idx] = lv;
    }
}

// =====================================================================
// Launch
// inputs: 0 query, 1 key, 2 value, 3 in_proj_w, 4 conv_w, 5 conv_b,
//         6 dt_bias, 7 A_log, 8 D, 9 norm_w, 10 out_proj_w
// =====================================================================
extern "C" void kernel_launch(void* const* d_in, const int* in_sizes, int n_in,
                              void* d_out, int out_size)
{
    const float* q          = (const float*)d_in[0];
    const float* in_proj_w  = (const float*)d_in[3];
    const float* conv_w     = (const float*)d_in[4];
    const float* conv_b     = (const float*)d_in[5];
    const float* dt_bias    = (const float*)d_in[6];
    const float* A_log      = (const float*)d_in[7];
    const float* Dvec       = (const float*)d_in[8];
    const float* norm_w     = (const float*)d_in[9];
    const float* out_proj_w = (const float*)d_in[10];
    float* out              = (float*)d_out;

    float* zxb; cudaGetSymbolAddress((void**)&zxb, g_zxb);
    __half *qh, *ql, *w1h, *w1l, *ynh, *ynl, *w2h, *w2l;
    cudaGetSymbolAddress((void**)&qh,  g_qh);
    cudaGetSymbolAddress((void**)&ql,  g_ql);
    cudaGetSymbolAddress((void**)&w1h, g_w1h);
    cudaGetSymbolAddress((void**)&w1l, g_w1l);
    cudaGetSymbolAddress((void**)&ynh, g_ynh);
    cudaGetSymbolAddress((void**)&ynl, g_ynl);
    cudaGetSymbolAddress((void**)&w2h, g_w2h);
    cudaGetSymbolAddress((void**)&w2l, g_w2l);

    cudaFuncSetAttribute(gemm_mma, cudaFuncAttributeMaxDynamicSharedMemorySize, GEMM_SMEM);
    cudaFuncSetAttribute(ssd_state_kernel, cudaFuncAttributeMaxDynamicSharedMemorySize, SSDA_SMEM);
    cudaFuncSetAttribute(ssd_out_kernel, cudaFuncAttributeMaxDynamicSharedMemorySize, SSDO_SMEM);

    // 0) split-convert GEMM operands (fp16 hi/lo)
    {
        const int nq = ROWS * D_MODEL / 4;
        cvt_pair<<<(nq + 255)/256, 256>>>(q, qh, ql, nq);
        const int nw1 = N_MAIN * D_MODEL / 4;
        cvt_pair<<<(nw1 + 255)/256, 256>>>(in_proj_w, w1h, w1l, nw1);
        const int nw2 = D_MODEL * D_INNER / 4;
        cvt_pair<<<(nw2 + 255)/256, 256>>>(out_proj_w, w2h, w2l, nw2);
    }

    // 0b) exact fp32 dt projection (last 32 columns; the error-amplified path)
    dtproj_kernel<<<ROWS/8, 256>>>(q, in_proj_w);

    // 1) zxbcdt[:, :4352] = q @ in_proj_w[:4352]^T  (fp16 2-term HMMA)
    gemm_mma<<<dim3(N_MAIN/256, ROWS/128), 256, GEMM_SMEM>>>(
        qh, ql, w1h, zxb, ROWS, N_MAIN, D_MODEL, D_IN_PROJ);

    // 2) causal conv4 + SiLU
    conv_silu_kernel<<<dim3(CONV_DIM/256, SEQ/128, BATCH), 256>>>(conv_w, conv_b);

    // 3) dt / la
    dt_kernel<<<(NBH*SEQ + 255)/256, 256>>>(dt_bias, A_log);

    // 4) SSD chunked scan (GEMM-formulated, 3 phases)
    ssd_state_kernel<<<dim3(NCHUNK, NBH), 256, SSDA_SMEM>>>();
    chunk_combine_kernel<<<NBH, 256>>>();
    ssd_out_kernel<<<dim3(NCHUNK, NBH), 256, SSDO_SMEM>>>(Dvec);

    // 5) gate + RMSNorm (emits fp16 hi/lo)
    gate_norm_kernel<<<ROWS, 256>>>(norm_w);

    // 6) out = yn @ out_proj_w^T  (fp16 2-term HMMA)
    gemm_mma<<<dim3(D_MODEL/256, ROWS/128), 256, GEMM_SMEM>>>(
        ynh, ynl, w2h, out, ROWS, D_MODEL, D_INNER, D_MODEL);
}

// round 13
// speedup vs baseline: 1.5474x; 1.5474x over previous
#include <cuda_runtime.h>
#include <cuda_fp16.h>
#include <cstdint>
#include <math.h>

// ---------------- Problem constants ----------------
#define D_MODEL   1024
#define HEADDIM   64
#define D_STATE   128
#define D_INNER   2048
#define NHEADS    32
#define CONV_DIM  2304           // D_INNER + 2*D_STATE
#define D_IN_PROJ 4384           // 2*D_INNER + 2*D_STATE + NHEADS
#define N_MAIN    4352           // D_IN_PROJ - NHEADS (cols via fp16 GEMM)
#define BATCH     4
#define SEQ       2048
#define ROWS      (BATCH*SEQ)    // 8192
#define EPSV      1e-5f

#define NCHUNK    16
#define LCH       128
#define NBH       (BATCH*NHEADS) // 128
#define STATE_SZ  (HEADDIM*D_STATE)  // 8192

#define PR  132                  // padded 128-float row
#define PX  68                   // padded 64-float row

typedef unsigned long long ull;

// ---------------- Scratch ----------------
__device__ float g_zxb[(size_t)ROWS * D_IN_PROJ];
__device__ float g_xbc[(size_t)ROWS * CONV_DIM];
__device__ float g_dtraw[(size_t)ROWS * NHEADS];    // exact fp32 dt projection
__device__ float g_dt [NBH*SEQ];
__device__ float g_la [NBH*SEQ];                    // A*dt (log dA)
__device__ float g_yb [(size_t)ROWS * D_INNER];

__device__ float g_st  [(size_t)NBH * NCHUNK * STATE_SZ];
__device__ float g_hini[(size_t)NBH * NCHUNK * STATE_SZ];
__device__ float g_cum [NBH * NCHUNK];

// fp16 split operands for tensor-core GEMMs
__device__ __half g_qh [(size_t)ROWS * D_MODEL];
__device__ __half g_ql [(size_t)ROWS * D_MODEL];
__device__ __half g_w1h[(size_t)N_MAIN * D_MODEL];
__device__ __half g_w1l[(size_t)N_MAIN * D_MODEL];
__device__ __half g_ynh[(size_t)ROWS * D_INNER];
__device__ __half g_ynl[(size_t)ROWS * D_INNER];
__device__ __half g_w2h[(size_t)D_MODEL * D_INNER];
__device__ __half g_w2l[(size_t)D_MODEL * D_INNER];

// ---------------- f32x2 packed helpers ----------------
__device__ __forceinline__ ull pack2(float lo, float hi) {
    ull r; asm("mov.b64 %0, {%1,%2};" : "=l"(r) : "f"(lo), "f"(hi)); return r;
}
__device__ __forceinline__ void unpack2(ull v, float& lo, float& hi) {
    asm("mov.b64 {%0,%1}, %2;" : "=f"(lo), "=f"(hi) : "l"(v));
}
__device__ __forceinline__ void fma2(ull& d, ull a, ull b) {
    asm("fma.rn.f32x2 %0, %1, %2, %0;" : "+l"(d) : "l"(a), "l"(b));
}
__device__ __forceinline__ ull mul2(ull a, ull b) {
    ull r; asm("mul.rn.f32x2 %0, %1, %2;" : "=l"(r) : "l"(a), "l"(b)); return r;
}
#define COMP(v,k) ((k)==0?(v).x:((k)==1?(v).y:((k)==2?(v).z:(v).w)))

// ---------------- cp.async helpers ----------------
__device__ __forceinline__ void cp16(unsigned s, const void* g) {
    asm volatile("cp.async.ca.shared.global [%0], [%1], 16;" :: "r"(s), "l"(g));
}
__device__ __forceinline__ void cp_commit() { asm volatile("cp.async.commit_group;"); }
template<int N> __device__ __forceinline__ void cp_wait() {
    asm volatile("cp.async.wait_group %0;" :: "n"(N));
}
__device__ __forceinline__ unsigned smem_u32(const void* p) {
    return (unsigned)__cvta_generic_to_shared(p);
}

// ---------------- mma.sync + ldmatrix (fp16) ----------------
#define LDSM4(r, addr) \
    asm volatile("ldmatrix.sync.aligned.m8n8.x4.shared.b16 {%0,%1,%2,%3}, [%4];" \
        : "=r"((r)[0]), "=r"((r)[1]), "=r"((r)[2]), "=r"((r)[3]) : "r"(addr))

#define MMA16816H(d, a, b) \
    asm volatile("mma.sync.aligned.m16n8k16.row.col.f32.f16.f16.f32 " \
        "{%0,%1,%2,%3}, {%4,%5,%6,%7}, {%8,%9}, {%0,%1,%2,%3};" \
        : "+f"((d)[0]), "+f"((d)[1]), "+f"((d)[2]), "+f"((d)[3]) \
        : "r"((a)[0]), "r"((a)[1]), "r"((a)[2]), "r"((a)[3]), \
          "r"((b)[0]), "r"((b)[1]))

// =====================================================================
// Split-fp16 HMMA GEMM (NT): C = Ah*Bh + Al*Bh   (fp32 accum)
// CTA tile 128(M) x 256(N), BK=64, 3-stage cp.async pipeline.
// Stage layout (64KB): Ah@0 16K | Al@16K | Bh@32K 32K
// =====================================================================
#define GEMM_STG   65536
#define GEMM_SMEM  (3*GEMM_STG)

__global__ void __launch_bounds__(256, 1)
gemm_mma(const __half* __restrict__ A_h, const __half* __restrict__ A_l,
         const __half* __restrict__ B_h,
         float* __restrict__ C, int M, int N, int K, int ldC)
{
    extern __shared__ __align__(1024) char sm[];
    const unsigned base = smem_u32(sm);
    const int tid  = threadIdx.x;
    const int lane = tid & 31;
    const int wid  = tid >> 5;
    const int wm   = wid >> 2;
    const int wn   = wid & 3;
    const int m0   = blockIdx.y * 128;
    const int n0   = blockIdx.x * 256;

    float acc[4][8][4];
#pragma unroll
    for (int t = 0; t < 4; t++)
#pragma unroll
        for (int u = 0; u < 8; u++)
#pragma unroll
            for (int v = 0; v < 4; v++) acc[t][u][v] = 0.f;

    auto load_stage = [&](int s, unsigned stg) {
        const int k0 = s * 64;
#pragma unroll
        for (int i = 0; i < 4; i++) {
            const int ch = tid + i * 256;
            const int row = ch >> 3, c = ch & 7;
            const unsigned off = (unsigned)(row * 128) + ((unsigned)(c ^ (row & 7)) << 4);
            const size_t g = (size_t)(m0 + row) * K + k0 + c * 8;
            cp16(stg + off,         A_h + g);
            cp16(stg + 16384 + off, A_l + g);
        }
#pragma unroll
        for (int i = 0; i < 8; i++) {
            const int ch = tid + i * 256;
            const int row = ch >> 3, c = ch & 7;
            const unsigned off = (unsigned)(row * 128) + ((unsigned)(c ^ (row & 7)) << 4);
            const size_t g = (size_t)(n0 + row) * K + k0 + c * 8;
            cp16(stg + 32768 + off, B_h + g);
        }
        cp_commit();
    };

    const int S = K / 64;
    load_stage(0, base);
    if (S > 1) load_stage(1, base + GEMM_STG);

    for (int s = 0; s < S; s++) {
        const unsigned stg = base + (unsigned)(s % 3) * GEMM_STG;
        if (s + 2 < S) { load_stage(s + 2, base + (unsigned)((s + 2) % 3) * GEMM_STG); cp_wait<2>(); }
        else if (s + 1 < S) { cp_wait<1>(); }
        else { cp_wait<0>(); }
        __syncthreads();

        const unsigned stgA  = stg;
        const unsigned stgAl = stg + 16384;
        const unsigned stgB  = stg + 32768;

#pragma unroll
        for (int ks = 0; ks < 4; ks++) {
            unsigned ah[4][4], al[4][4], bb[8][2];
            const unsigned akoff = ((unsigned)((ks * 2 + (lane >> 4)) ^ (lane & 7))) << 4;
#pragma unroll
            for (int t = 0; t < 4; t++) {
                const unsigned ro = (unsigned)((wm * 64 + t * 16 + (lane & 15)) * 128);
                LDSM4(ah[t], stgA  + ro + akoff);
                LDSM4(al[t], stgAl + ro + akoff);
            }
            const unsigned bkoff = ((unsigned)((ks * 2 + ((lane >> 3) & 1)) ^ (lane & 7))) << 4;
#pragma unroll
            for (int p = 0; p < 4; p++) {
                const unsigned ro = (unsigned)((wn * 64 + p * 16 + (lane & 7) + ((lane & 16) >> 1)) * 128);
                unsigned r[4];
                LDSM4(r, stgB + ro + bkoff);
                bb[2*p][0] = r[0]; bb[2*p][1] = r[1];
                bb[2*p+1][0] = r[2]; bb[2*p+1][1] = r[3];
            }
#pragma unroll
            for (int t = 0; t < 4; t++)
#pragma unroll
                for (int u = 0; u < 8; u++) {
                    MMA16816H(acc[t][u], ah[t], bb[u]);
                    MMA16816H(acc[t][u], al[t], bb[u]);
                }
        }
        __syncthreads();
    }

#pragma unroll
    for (int t = 0; t < 4; t++) {
        const int row = m0 + wm * 64 + t * 16 + (lane >> 2);
#pragma unroll
        for (int u = 0; u < 8; u++) {
            const int col = n0 + wn * 64 + u * 8 + (lane & 3) * 2;
            if (col < N) {
                *(float2*)(C + (size_t)row * ldC + col)       = make_float2(acc[t][u][0], acc[t][u][1]);
                *(float2*)(C + (size_t)(row + 8) * ldC + col) = make_float2(acc[t][u][2], acc[t][u][3]);
            }
        }
    }
}

// =====================================================================
// fp32 -> (fp16 hi, fp16 lo) split conversion
// =====================================================================
__global__ void __launch_bounds__(256) cvt_pair(const float* __restrict__ src,
                                                __half* __restrict__ h,
                                                __half* __restrict__ l, int n4)
{
    const int i = blockIdx.x * 256 + threadIdx.x;
    if (i >= n4) return;
    const float4 v = ((const float4*)src)[i];
    __half h0 = __float2half_rn(v.x), h1 = __float2half_rn(v.y),
           h2 = __float2half_rn(v.z), h3 = __float2half_rn(v.w);
    __half l0 = __float2half_rn(v.x - __half2float(h0));
    __half l1 = __float2half_rn(v.y - __half2float(h1));
    __half l2 = __float2half_rn(v.z - __half2float(h2));
    __half l3 = __float2half_rn(v.w - __half2float(h3));
    ushort4 hv = make_ushort4(__half_as_ushort(h0), __half_as_ushort(h1),
                              __half_as_ushort(h2), __half_as_ushort(h3));
    ushort4 lv = make_ushort4(__half_as_ushort(l0), __half_as_ushort(l1),
                              __half_as_ushort(l2), __half_as_ushort(l3));
    ((ushort4*)h)[i] = hv;
    ((ushort4*)l)[i] = lv;
}

// =====================================================================
// Exact fp32 dt projection (smem-tiled mini-GEMM, coalesced)
// dtraw[r][c] = q[r] . w1[N_MAIN + c],  c < 32.
// grid 128 CTAs x 64 rows, 256 threads.
// thread: rg = tid>>4 (4 rows: rg*4..+3), cp = tid&15 (cols 2cp, 2cp+1)
// =====================================================================
#define DTP_RPC 64
#define SQ_LD   36
#define SW_LD   34

__global__ void __launch_bounds__(256) dtproj_kernel(const float* __restrict__ q,
                                                     const float* __restrict__ w1)
{
    __shared__ float sq[DTP_RPC * SQ_LD];   // [row][36]
    __shared__ float sW[32 * SW_LD];        // [k][34]  (transposed weights)

    const int tid = threadIdx.x;
    const int r0  = blockIdx.x * DTP_RPC;
    const int rg  = tid >> 4;               // 0..15 -> rows rg*4..rg*4+3
    const int cp  = tid & 15;               // col pair

    ull acc[4];
#pragma unroll
    for (int i = 0; i < 4; i++) acc[i] = 0ull;

    for (int k0 = 0; k0 < D_MODEL; k0 += 32) {
        __syncthreads();
        // q tile: 64 rows x 32 k  (coalesced 128B segments)
        {
            const int row = tid >> 3;        // 0..31
            const int kk  = (tid & 7) * 4;
#pragma unroll
            for (int i = 0; i < 2; i++) {
                const int r = row + i * 32;
                float4 v = *(const float4*)(q + (size_t)(r0 + r) * D_MODEL + k0 + kk);
                *(float4*)(sq + r * SQ_LD + kk) = v;
            }
        }
        // w tile: 32 cols x 32 k, stored transposed [k][c]
        {
            const int c  = tid >> 3;         // 0..31
            const int kk = (tid & 7) * 4;
            float4 v = *(const float4*)(w1 + ((size_t)N_MAIN + c) * D_MODEL + k0 + kk);
            sW[(kk + 0) * SW_LD + c] = v.x;
            sW[(kk + 1) * SW_LD + c] = v.y;
            sW[(kk + 2) * SW_LD + c] = v.z;
            sW[(kk + 3) * SW_LD + c] = v.w;
        }
        __syncthreads();

#pragma unroll 8
        for (int k = 0; k < 32; k += 4) {
            ull wq[4];
#pragma unroll
            for (int j = 0; j < 4; j++)
                wq[j] = *(const ull*)(sW + (k + j) * SW_LD + cp * 2);
#pragma unroll
            for (int i = 0; i < 4; i++) {
                const float4 qv = *(const float4*)(sq + (rg * 4 + i) * SQ_LD + k);
                fma2(acc[i], pack2(qv.x, qv.x), wq[0]);
                fma2(acc[i], pack2(qv.y, qv.y), wq[1]);
                fma2(acc[i], pack2(qv.z, qv.z), wq[2]);
                fma2(acc[i], pack2(qv.w, qv.w), wq[3]);
            }
        }
    }

#pragma unroll
    for (int i = 0; i < 4; i++) {
        float lo, hi; unpack2(acc[i], lo, hi);
        const int row = r0 + rg * 4 + i;
        *(float2*)(g_dtraw + (size_t)row * NHEADS + cp * 2) = make_float2(lo, hi);
    }
}

// =====================================================================
// Depthwise causal conv (width 4) + SiLU
// =====================================================================
__global__ void __launch_bounds__(256) conv_silu_kernel(const float* __restrict__ conv_w,
                                                        const float* __restrict__ conv_b)
{
    const int c  = blockIdx.x * 256 + threadIdx.x;
    const int l0 = blockIdx.y * 128;
    const int b  = blockIdx.z;

    const float w0 = conv_w[c*4+0], w1 = conv_w[c*4+1],
                w2 = conv_w[c*4+2], w3 = conv_w[c*4+3];
    const float bias = conv_b[c];

    const float* src = g_zxb + (size_t)(b*SEQ) * D_IN_PROJ + D_INNER + c;
    float*       dst = g_xbc + (size_t)(b*SEQ) * CONV_DIM + c;

    float xm3 = (l0-3 >= 0) ? src[(size_t)(l0-3) * D_IN_PROJ] : 0.f;
    float xm2 = (l0-2 >= 0) ? src[(size_t)(l0-2) * D_IN_PROJ] : 0.f;
    float xm1 = (l0-1 >= 0) ? src[(size_t)(l0-1) * D_IN_PROJ] : 0.f;

    for (int l = l0; l < l0 + 128; l++) {
        const float xc = src[(size_t)l * D_IN_PROJ];
        float v = bias + w0*xm3 + w1*xm2 + w2*xm1 + w3*xc;
        v = v / (1.f + expf(-v));
        dst[(size_t)l * CONV_DIM] = v;
        xm3 = xm2; xm2 = xm1; xm1 = xc;
    }
}

// =====================================================================
// dt = softplus(dtraw + dt_bias); la = A*dt   layout [bh][l]
// =====================================================================
__global__ void __launch_bounds__(256) dt_kernel(const float* __restrict__ dt_bias,
                                                 const float* __restrict__ A_log)
{
    const int idx = blockIdx.x * 256 + threadIdx.x;
    if (idx >= NBH*SEQ) return;
    const int l = idx & (SEQ-1);
    const int h = (idx >> 11) & (NHEADS-1);
    const int b = idx >> 16;
    const float raw = g_dtraw[(size_t)(b*SEQ + l) * NHEADS + h] + dt_bias[h];
    const float sp = (raw > 20.f) ? raw : log1pf(expf(raw));
    const float Ahv = -expf(A_log[h]);
    g_dt[idx] = sp;
    g_la[idx] = Ahv * sp;
}

// =====================================================================
// SSD phase 1: per-chunk final local state via outer-product GEMM.
// =====================================================================
#define SSDA_SMEM ((128*PR + 128*PX + 384) * 4)

__global__ void __launch_bounds__(256, 2) ssd_state_kernel()
{
    extern __shared__ float sma[];
    float* sB  = sma;                 // [128][PR]
    float* sVW = sB + 128*PR;         // [128][PX]  dt*w*x
    float* sCS = sVW + 128*PX;        // [128]
    float* sDT = sCS + 128;           // [128]
    float* sLA = sDT + 128;           // [128]

    const int ck = blockIdx.x, bh = blockIdx.y;
    const int b  = bh >> 5, hh = bh & 31;
    const int tid = threadIdx.x;
    const size_t rbase = (size_t)(b*SEQ + ck*LCH);

#pragma unroll
    for (int i = 0; i < 16; i++) {
        int idx = i*256 + tid; int t = idx >> 5, f4 = idx & 31;
        cp16(smem_u32(sB + t*PR + f4*4),
             g_xbc + (rbase + t)*CONV_DIM + D_INNER + f4*4);
    }
#pragma unroll
    for (int i = 0; i < 8; i++) {
        int idx = i*256 + tid; int t = idx >> 4, f4 = idx & 15;
        cp16(smem_u32(sVW + t*PX + f4*4),
             g_xbc + (rbase + t)*CONV_DIM + hh*HEADDIM + f4*4);
    }
    if (tid < 128) {
        sDT[tid] = g_dt[(size_t)bh*SEQ + ck*LCH + tid];
        sLA[tid] = g_la[(size_t)bh*SEQ + ck*LCH + tid];
    }
    cp_commit(); cp_wait<0>();
    __syncthreads();
    if (tid == 0) {
        float c = 0.f;
        for (int s = 0; s < 128; s++) { c += sLA[s]; sCS[s] = c; }
    }
    __syncthreads();
    const float csL = sCS[127];
    if (tid < 128) {
        const float w = __expf(csL - sCS[tid]) * sDT[tid];
        float* row = sVW + tid*PX;
#pragma unroll
        for (int p = 0; p < 64; p += 4) {
            float4 v = *(float4*)(row + p);
            v.x *= w; v.y *= w; v.z *= w; v.w *= w;
            *(float4*)(row + p) = v;
        }
    }
    if (tid == 0) g_cum[bh*NCHUNK + ck] = __expf(csL);
    __syncthreads();

    const int pg = tid >> 4;
    const int ng = tid & 15;

    ull Sp[4][4];
#pragma unroll
    for (int i = 0; i < 4; i++)
#pragma unroll
        for (int q = 0; q < 4; q++) Sp[i][q] = 0ull;

#pragma unroll 4
    for (int s = 0; s < 128; s++) {
        const float4 v4  = *(const float4*)(sVW + s*PX + pg*4);
        const float4 b40 = *(const float4*)(sB + s*PR + ng*8);
        const float4 b41 = *(const float4*)(sB + s*PR + ng*8 + 4);
        ull bp[4] = { pack2(b40.x, b40.y), pack2(b40.z, b40.w),
                      pack2(b41.x, b41.y), pack2(b41.z, b41.w) };
#pragma unroll
        for (int i = 0; i < 4; i++) {
            const float vv = COMP(v4, i);
            const ull vc = pack2(vv, vv);
#pragma unroll
            for (int q = 0; q < 4; q++) fma2(Sp[i][q], vc, bp[q]);
        }
    }

    float* dst = g_st + (size_t)(bh*NCHUNK + ck)*STATE_SZ;
#pragma unroll
    for (int i = 0; i < 4; i++) {
        const int p = pg*4 + i;
        float o[8];
#pragma unroll
        for (int q = 0; q < 4; q++) unpack2(Sp[i][q], o[q*2], o[q*2+1]);
        *(float4*)(dst + p*D_STATE + ng*8)     = make_float4(o[0], o[1], o[2], o[3]);
        *(float4*)(dst + p*D_STATE + ng*8 + 4) = make_float4(o[4], o[5], o[6], o[7]);
    }
}

// =====================================================================
// SSD phase 2: combine across chunks.
// =====================================================================
__global__ void __launch_bounds__(256) chunk_combine_kernel()
{
    const int bh  = blockIdx.x;
    const int tid = threadIdx.x;
    const size_t off = tid * 32;

    float4 h[8];
#pragma unroll
    for (int i = 0; i < 8; i++) h[i] = make_float4(0.f, 0.f, 0.f, 0.f);

    for (int ck = 0; ck < NCHUNK; ck++) {
        float4* hi = (float4*)(g_hini + (size_t)(bh * NCHUNK + ck) * STATE_SZ + off);
#pragma unroll
        for (int i = 0; i < 8; i++) hi[i] = h[i];
        if (ck < NCHUNK - 1) {
            const float a = g_cum[bh * NCHUNK + ck];
            const float4* s = (const float4*)(g_st + (size_t)(bh * NCHUNK + ck) * STATE_SZ + off);
#pragma unroll
            for (int i = 0; i < 8; i++) {
                float4 sv = s[i];
                h[i].x = a * h[i].x + sv.x;
                h[i].y = a * h[i].y + sv.y;
                h[i].z = a * h[i].z + sv.z;
                h[i].w = a * h[i].w + sv.w;
            }
        }
    }
}

// =====================================================================
// SSD phase 3: per-chunk outputs via GEMMs.
// =====================================================================
#define SSDO_SMEM ((2*128*PR + 128*PX + 64*PR + 384) * 4)

__global__ void __launch_bounds__(256, 1) ssd_out_kernel(const float* __restrict__ Dvec)
{
    extern __shared__ float smo[];
    float* sC  = smo;                  // [128][PR]  (reused as sXT [64][PR])
    float* sB  = sC + 128*PR;          // [128][PR]  (reused as M)
    float* sX  = sB + 128*PR;          // [128][PX]
    float* sH  = sX + 128*PX;          // [64][PR]
    float* sCS = sH + 64*PR;           // [128]
    float* sDT = sCS + 128;            // [128]
    float* sLA = sDT + 128;            // [128]
    float* sXT = sC;

    const int ck = blockIdx.x, bh = blockIdx.y;
    const int b  = bh >> 5, hh = bh & 31;
    const int tid = threadIdx.x;
    const size_t rbase = (size_t)(b*SEQ + ck*LCH);

#pragma unroll
    for (int i = 0; i < 16; i++) {
        int idx = i*256 + tid; int t = idx >> 5, f4 = idx & 31;
        const float* row = g_xbc + (rbase + t)*CONV_DIM;
        cp16(smem_u32(sC + t*PR + f4*4), row + D_INNER + D_STATE + f4*4);
        cp16(smem_u32(sB + t*PR + f4*4), row + D_INNER + f4*4);
    }
#pragma unroll
    for (int i = 0; i < 8; i++) {
        int idx = i*256 + tid; int t = idx >> 4, f4 = idx & 15;
        cp16(smem_u32(sX + t*PX + f4*4),
             g_xbc + (rbase + t)*CONV_DIM + hh*HEADDIM + f4*4);
    }
    {
        const float* hsrc = g_hini + (size_t)(bh*NCHUNK + ck)*STATE_SZ;
#pragma unroll
        for (int i = 0; i < 8; i++) {
            int idx = i*256 + tid; int p = idx >> 5, f4 = idx & 31;
            cp16(smem_u32(sH + p*PR + f4*4), hsrc + p*D_STATE + f4*4);
        }
    }
    if (tid < 128) {
        sDT[tid] = g_dt[(size_t)bh*SEQ + ck*LCH + tid];
        sLA[tid] = g_la[(size_t)bh*SEQ + ck*LCH + tid];
    }
    cp_commit(); cp_wait<0>();
    __syncthreads();
    if (tid == 0) {
        float c = 0.f;
        for (int s = 0; s < 128; s++) { c += sLA[s]; sCS[s] = c; }
    }
    __syncthreads();

    const int tt = tid >> 4;
    const int tp = tid & 15;

    ull Yp[8][2];
#pragma unroll
    for (int i = 0; i < 8; i++) { Yp[i][0] = 0ull; Yp[i][1] = 0ull; }
    ull Gp[8][4];
#pragma unroll
    for (int i = 0; i < 8; i++)
#pragma unroll
        for (int q = 0; q < 4; q++) Gp[i][q] = 0ull;

    for (int n4 = 0; n4 < 32; n4++) {
        float4 c4[8], h4[4], b4[8];
#pragma unroll
        for (int i = 0; i < 8; i++) c4[i] = *(const float4*)(sC + (tt*8+i)*PR + n4*4);
#pragma unroll
        for (int j = 0; j < 4; j++) h4[j] = *(const float4*)(sH + (tp+16*j)*PR + n4*4);
#pragma unroll
        for (int m = 0; m < 8; m++) b4[m] = *(const float4*)(sB + (tp+16*m)*PR + n4*4);
#pragma unroll
        for (int k = 0; k < 4; k++) {
            ull hq[2] = { pack2(COMP(h4[0],k), COMP(h4[1],k)),
                          pack2(COMP(h4[2],k), COMP(h4[3],k)) };
            ull bq[4];
#pragma unroll
            for (int q = 0; q < 4; q++)
                bq[q] = pack2(COMP(b4[2*q],k), COMP(b4[2*q+1],k));
#pragma unroll
            for (int i = 0; i < 8; i++) {
                const float cv = COMP(c4[i], k);
                const ull cc = pack2(cv, cv);
                fma2(Yp[i][0], cc, hq[0]);
                fma2(Yp[i][1], cc, hq[1]);
#pragma unroll
                for (int q = 0; q < 4; q++) fma2(Gp[i][q], cc, bq[q]);
            }
        }
    }

#pragma unroll
    for (int i = 0; i < 8; i++) {
        const float w = __expf(sCS[tt*8 + i]);
        const ull ww = pack2(w, w);
        Yp[i][0] = mul2(Yp[i][0], ww);
        Yp[i][1] = mul2(Yp[i][1], ww);
    }

    __syncthreads();

#pragma unroll
    for (int i = 0; i < 8; i++) {
        const int t = tt*8 + i;
        const float et = sCS[t];
#pragma unroll
        for (int q = 0; q < 4; q++) {
            float g0, g1; unpack2(Gp[i][q], g0, g1);
            const int s0 = tp + 16*(2*q);
            const int s1 = tp + 16*(2*q + 1);
            sB[t*PR + s0] = (s0 <= t) ? g0 * __expf(et - sCS[s0]) * sDT[s0] : 0.f;
            sB[t*PR + s1] = (s1 <= t) ? g1 * __expf(et - sCS[s1]) * sDT[s1] : 0.f;
        }
    }
#pragma unroll
    for (int i = 0; i < 32; i++) {
        int e = i*256 + tid; int s = e >> 6, p = e & 63;
        sXT[p*PR + s] = sX[s*PX + p];
    }
    __syncthreads();

    for (int s4 = 0; s4 < 32; s4++) {
        float4 m4[8], x4[4];
#pragma unroll
        for (int i = 0; i < 8; i++) m4[i] = *(const float4*)(sB + (tt*8+i)*PR + s4*4);
#pragma unroll
        for (int j = 0; j < 4; j++) x4[j] = *(const float4*)(sXT + (tp+16*j)*PR + s4*4);
#pragma unroll
        for (int k = 0; k < 4; k++) {
            ull xq[2] = { pack2(COMP(x4[0],k), COMP(x4[1],k)),
                          pack2(COMP(x4[2],k), COMP(x4[3],k)) };
#pragma unroll
            for (int i = 0; i < 8; i++) {
                const float mv = COMP(m4[i], k);
                const ull mm = pack2(mv, mv);
                fma2(Yp[i][0], mm, xq[0]);
                fma2(Yp[i][1], mm, xq[1]);
            }
        }
    }

    const float Dv = Dvec[hh];
#pragma unroll
    for (int i = 0; i < 8; i++) {
        const int t = tt*8 + i;
        float* orow = g_yb + ((rbase + t) * NHEADS + hh) * HEADDIM;
        float y0, y1, y2, y3;
        unpack2(Yp[i][0], y0, y1);
        unpack2(Yp[i][1], y2, y3);
        orow[tp]      = y0 + Dv * sX[t*PX + tp];
        orow[tp + 16] = y1 + Dv * sX[t*PX + tp + 16];
        orow[tp + 32] = y2 + Dv * sX[t*PX + tp + 32];
        orow[tp + 48] = y3 + Dv * sX[t*PX + tp + 48];
    }
}

// =====================================================================
// y = yb * silu(z); rmsnorm; write fp16 hi/lo split (GEMM2 A operand)
// =====================================================================
__global__ void __launch_bounds__(256) gate_norm_kernel(const float* __restrict__ norm_w)
{
    const int row = blockIdx.x;
    const int tid = threadIdx.x;
    const float* yb = g_yb + (size_t)row * D_INNER;
    const float* zr = g_zxb + (size_t)row * D_IN_PROJ;

    float4 v[2];
    float ss = 0.f;
#pragma unroll
    for (int j = 0; j < 2; j++) {
        const int idx = tid + j*256;        // float4 index
        const float4 z4 = ((const float4*)zr)[idx];
        const float4 y4 = ((const float4*)yb)[idx];
        float4 val;
        val.x = y4.x * (z4.x / (1.f + expf(-z4.x)));
        val.y = y4.y * (z4.y / (1.f + expf(-z4.y)));
        val.z = y4.z * (z4.z / (1.f + expf(-z4.z)));
        val.w = y4.w * (z4.w / (1.f + expf(-z4.w)));
        v[j] = val;
        ss += val.x*val.x + val.y*val.y + val.z*val.z + val.w*val.w;
    }
#pragma unroll
    for (int o = 16; o > 0; o >>= 1) ss += __shfl_xor_sync(0xffffffffu, ss, o);

    __shared__ float red[8];
    __shared__ float sscale;
    if ((tid & 31) == 0) red[tid >> 5] = ss;
    __syncthreads();
    if (tid == 0) {
        float tot = 0.f;
#pragma unroll
        for (int i = 0; i < 8; i++) tot += red[i];
        sscale = rsqrtf(tot / (float)D_INNER + EPSV);
    }
    __syncthreads();
    const float scale = sscale;

    __half* oh = g_ynh + (size_t)row * D_INNER;
    __half* ol = g_ynl + (size_t)row * D_INNER;
#pragma unroll
    for (int j = 0; j < 2; j++) {
        const int idx = tid + j*256;
        const float4 w4 = ((const float4*)norm_w)[idx];
        float y[4] = { v[j].x * scale * w4.x, v[j].y * scale * w4.y,
                       v[j].z * scale * w4.z, v[j].w * scale * w4.w };
        ushort4 hv, lv;
        __half h0 = __float2half_rn(y[0]); hv.x = __half_as_ushort(h0);
        __half h1 = __float2half_rn(y[1]); hv.y = __half_as_ushort(h1);
        __half h2 = __float2half_rn(y[2]); hv.z = __half_as_ushort(h2);
        __half h3 = __float2half_rn(y[3]); hv.w = __half_as_ushort(h3);
        lv.x = __half_as_ushort(__float2half_rn(y[0] - __half2float(h0)));
        lv.y = __half_as_ushort(__float2half_rn(y[1] - __half2float(h1)));
        lv.z = __half_as_ushort(__float2half_rn(y[2] - __half2float(h2)));
        lv.w = __half_as_ushort(__float2half_rn(y[3] - __half2float(h3)));
        ((ushort4*)oh)[idx] = hv;
        ((ushort4*)ol)[idx] = lv;
    }
}

// =====================================================================
// Launch
// inputs: 0 query, 1 key, 2 value, 3 in_proj_w, 4 conv_w, 5 conv_b,
//         6 dt_bias, 7 A_log, 8 D, 9 norm_w, 10 out_proj_w
// =====================================================================
extern "C" void kernel_launch(void* const* d_in, const int* in_sizes, int n_in,
                              void* d_out, int out_size)
{
    const float* q          = (const float*)d_in[0];
    const float* in_proj_w  = (const float*)d_in[3];
    const float* conv_w     = (const float*)d_in[4];
    const float* conv_b     = (const float*)d_in[5];
    const float* dt_bias    = (const float*)d_in[6];
    const float* A_log      = (const float*)d_in[7];
    const float* Dvec       = (const float*)d_in[8];
    const float* norm_w     = (const float*)d_in[9];
    const float* out_proj_w = (const float*)d_in[10];
    float* out              = (float*)d_out;

    float* zxb; cudaGetSymbolAddress((void**)&zxb, g_zxb);
    __half *qh, *ql, *w1h, *w1l, *ynh, *ynl, *w2h, *w2l;
    cudaGetSymbolAddress((void**)&qh,  g_qh);
    cudaGetSymbolAddress((void**)&ql,  g_ql);
    cudaGetSymbolAddress((void**)&w1h, g_w1h);
    cudaGetSymbolAddress((void**)&w1l, g_w1l);
    cudaGetSymbolAddress((void**)&ynh, g_ynh);
    cudaGetSymbolAddress((void**)&ynl, g_ynl);
    cudaGetSymbolAddress((void**)&w2h, g_w2h);
    cudaGetSymbolAddress((void**)&w2l, g_w2l);

    cudaFuncSetAttribute(gemm_mma, cudaFuncAttributeMaxDynamicSharedMemorySize, GEMM_SMEM);
    cudaFuncSetAttribute(ssd_state_kernel, cudaFuncAttributeMaxDynamicSharedMemorySize, SSDA_SMEM);
    cudaFuncSetAttribute(ssd_out_kernel, cudaFuncAttributeMaxDynamicSharedMemorySize, SSDO_SMEM);

    // 0) split-convert GEMM operands (fp16 hi/lo)
    {
        const int nq = ROWS * D_MODEL / 4;
        cvt_pair<<<(nq + 255)/256, 256>>>(q, qh, ql, nq);
        const int nw1 = N_MAIN * D_MODEL / 4;
        cvt_pair<<<(nw1 + 255)/256, 256>>>(in_proj_w, w1h, w1l, nw1);
        const int nw2 = D_MODEL * D_INNER / 4;
        cvt_pair<<<(nw2 + 255)/256, 256>>>(out_proj_w, w2h, w2l, nw2);
    }

    // 0b) exact fp32 dt projection (last 32 columns; the error-amplified path)
    dtproj_kernel<<<ROWS/DTP_RPC, 256>>>(q, in_proj_w);

    // 1) zxbcdt[:, :4352] = q @ in_proj_w[:4352]^T  (fp16 2-term HMMA)
    gemm_mma<<<dim3(N_MAIN/256, ROWS/128), 256, GEMM_SMEM>>>(
        qh, ql, w1h, zxb, ROWS, N_MAIN, D_MODEL, D_IN_PROJ);

    // 2) causal conv4 + SiLU
    conv_silu_kernel<<<dim3(CONV_DIM/256, SEQ/128, BATCH), 256>>>(conv_w, conv_b);

    // 3) dt / la
    dt_kernel<<<(NBH*SEQ + 255)/256, 256>>>(dt_bias, A_log);

    // 4) SSD chunked scan (GEMM-formulated, 3 phases)
    ssd_state_kernel<<<dim3(NCHUNK, NBH), 256, SSDA_SMEM>>>();
    chunk_combine_kernel<<<NBH, 256>>>();
    ssd_out_kernel<<<dim3(NCHUNK, NBH), 256, SSDO_SMEM>>>(Dvec);

    // 5) gate + RMSNorm (emits fp16 hi/lo)
    gate_norm_kernel<<<ROWS, 256>>>(norm_w);

    // 6) out = yn @ out_proj_w^T  (fp16 2-term HMMA)
    gemm_mma<<<dim3(D_MODEL/256, ROWS/128), 256, GEMM_SMEM>>>(
        ynh, ynl, w2h, out, ROWS, D_MODEL, D_INNER, D_MODEL);
}

// round 14
// speedup vs baseline: 2.0043x; 1.2953x over previous
#include <cuda_runtime.h>
#include <cuda_fp16.h>
#include <cstdint>
#include <math.h>

// ---------------- Problem constants ----------------
#define D_MODEL   1024
#define HEADDIM   64
#define D_STATE   128
#define D_INNER   2048
#define NHEADS    32
#define CONV_DIM  2304           // D_INNER + 2*D_STATE
#define D_IN_PROJ 4384           // 2*D_INNER + 2*D_STATE + NHEADS
#define N_MAIN    4352           // D_IN_PROJ - NHEADS
#define BATCH     4
#define SEQ       2048
#define ROWS      (BATCH*SEQ)    // 8192
#define EPSV      1e-5f

#define NCHUNK    16
#define LCH       128
#define NBH       (BATCH*NHEADS) // 128
#define STATE_SZ  (HEADDIM*D_STATE)  // 8192

#define PR  132
#define PX  68

typedef unsigned long long ull;

// ---------------- Scratch ----------------
__device__ float g_zxb[(size_t)ROWS * D_IN_PROJ];
__device__ float g_xbc[(size_t)ROWS * CONV_DIM];
__device__ float g_dtraw[(size_t)ROWS * NHEADS];
__device__ float g_dt [NBH*SEQ];
__device__ float g_la [NBH*SEQ];
__device__ float g_yb [(size_t)ROWS * D_INNER];

__device__ float g_st  [(size_t)NBH * NCHUNK * STATE_SZ];
__device__ float g_cum [NBH * NCHUNK];

// fp16 copies for tensor-core SSD
__device__ __half g_cv_h[(size_t)ROWS * CONV_DIM];
__device__ __half g_cv_l[(size_t)ROWS * CONV_DIM];
__device__ __half g_h16h[(size_t)NBH * NCHUNK * STATE_SZ];
__device__ __half g_h16l[(size_t)NBH * NCHUNK * STATE_SZ];

// fp16 split operands for big GEMMs
__device__ __half g_qh [(size_t)ROWS * D_MODEL];
__device__ __half g_ql [(size_t)ROWS * D_MODEL];
__device__ __half g_w1h[(size_t)N_MAIN * D_MODEL];
__device__ __half g_w1l[(size_t)N_MAIN * D_MODEL];
__device__ __half g_ynh[(size_t)ROWS * D_INNER];
__device__ __half g_ynl[(size_t)ROWS * D_INNER];
__device__ __half g_w2h[(size_t)D_MODEL * D_INNER];
__device__ __half g_w2l[(size_t)D_MODEL * D_INNER];

// ---------------- f32x2 packed helpers ----------------
__device__ __forceinline__ ull pack2(float lo, float hi) {
    ull r; asm("mov.b64 %0, {%1,%2};" : "=l"(r) : "f"(lo), "f"(hi)); return r;
}
__device__ __forceinline__ void unpack2(ull v, float& lo, float& hi) {
    asm("mov.b64 {%0,%1}, %2;" : "=f"(lo), "=f"(hi) : "l"(v));
}
__device__ __forceinline__ void fma2(ull& d, ull a, ull b) {
    asm("fma.rn.f32x2 %0, %1, %2, %0;" : "+l"(d) : "l"(a), "l"(b));
}
__device__ __forceinline__ ull mul2(ull a, ull b) {
    ull r; asm("mul.rn.f32x2 %0, %1, %2;" : "=l"(r) : "l"(a), "l"(b)); return r;
}
#define COMP(v,k) ((k)==0?(v).x:((k)==1?(v).y:((k)==2?(v).z:(v).w)))

// ---------------- cp.async helpers ----------------
__device__ __forceinline__ void cp16(unsigned s, const void* g) {
    asm volatile("cp.async.ca.shared.global [%0], [%1], 16;" :: "r"(s), "l"(g));
}
__device__ __forceinline__ void cp_commit() { asm volatile("cp.async.commit_group;"); }
template<int N> __device__ __forceinline__ void cp_wait() {
    asm volatile("cp.async.wait_group %0;" :: "n"(N));
}
__device__ __forceinline__ unsigned smem_u32(const void* p) {
    return (unsigned)__cvta_generic_to_shared(p);
}

// ---------------- mma.sync + ldmatrix (fp16) ----------------
#define LDSM4(r, addr) \
    asm volatile("ldmatrix.sync.aligned.m8n8.x4.shared.b16 {%0,%1,%2,%3}, [%4];" \
        : "=r"((r)[0]), "=r"((r)[1]), "=r"((r)[2]), "=r"((r)[3]) : "r"(addr))

#define MMA16816H(d, a, b) \
    asm volatile("mma.sync.aligned.m16n8k16.row.col.f32.f16.f16.f32 " \
        "{%0,%1,%2,%3}, {%4,%5,%6,%7}, {%8,%9}, {%0,%1,%2,%3};" \
        : "+f"((d)[0]), "+f"((d)[1]), "+f"((d)[2]), "+f"((d)[3]) \
        : "r"((a)[0]), "r"((a)[1]), "r"((a)[2]), "r"((a)[3]), \
          "r"((b)[0]), "r"((b)[1]))

// =====================================================================
// Split-fp16 HMMA GEMM (NT): C = Ah*Bh + Al*Bh   (unchanged from R13)
// =====================================================================
#define GEMM_STG   65536
#define GEMM_SMEM  (3*GEMM_STG)

__global__ void __launch_bounds__(256, 1)
gemm_mma(const __half* __restrict__ A_h, const __half* __restrict__ A_l,
         const __half* __restrict__ B_h,
         float* __restrict__ C, int M, int N, int K, int ldC)
{
    extern __shared__ __align__(1024) char sm[];
    const unsigned base = smem_u32(sm);
    const int tid  = threadIdx.x;
    const int lane = tid & 31;
    const int wid  = tid >> 5;
    const int wm   = wid >> 2;
    const int wn   = wid & 3;
    const int m0   = blockIdx.y * 128;
    const int n0   = blockIdx.x * 256;

    float acc[4][8][4];
#pragma unroll
    for (int t = 0; t < 4; t++)
#pragma unroll
        for (int u = 0; u < 8; u++)
#pragma unroll
            for (int v = 0; v < 4; v++) acc[t][u][v] = 0.f;

    auto load_stage = [&](int s, unsigned stg) {
        const int k0 = s * 64;
#pragma unroll
        for (int i = 0; i < 4; i++) {
            const int ch = tid + i * 256;
            const int row = ch >> 3, c = ch & 7;
            const unsigned off = (unsigned)(row * 128) + ((unsigned)(c ^ (row & 7)) << 4);
            const size_t g = (size_t)(m0 + row) * K + k0 + c * 8;
            cp16(stg + off,         A_h + g);
            cp16(stg + 16384 + off, A_l + g);
        }
#pragma unroll
        for (int i = 0; i < 8; i++) {
            const int ch = tid + i * 256;
            const int row = ch >> 3, c = ch & 7;
            const unsigned off = (unsigned)(row * 128) + ((unsigned)(c ^ (row & 7)) << 4);
            const size_t g = (size_t)(n0 + row) * K + k0 + c * 8;
            cp16(stg + 32768 + off, B_h + g);
        }
        cp_commit();
    };

    const int S = K / 64;
    load_stage(0, base);
    if (S > 1) load_stage(1, base + GEMM_STG);

    for (int s = 0; s < S; s++) {
        const unsigned stg = base + (unsigned)(s % 3) * GEMM_STG;
        if (s + 2 < S) { load_stage(s + 2, base + (unsigned)((s + 2) % 3) * GEMM_STG); cp_wait<2>(); }
        else if (s + 1 < S) { cp_wait<1>(); }
        else { cp_wait<0>(); }
        __syncthreads();

        const unsigned stgA  = stg;
        const unsigned stgAl = stg + 16384;
        const unsigned stgB  = stg + 32768;

#pragma unroll
        for (int ks = 0; ks < 4; ks++) {
            unsigned ah[4][4], al[4][4], bb[8][2];
            const unsigned akoff = ((unsigned)((ks * 2 + (lane >> 4)) ^ (lane & 7))) << 4;
#pragma unroll
            for (int t = 0; t < 4; t++) {
                const unsigned ro = (unsigned)((wm * 64 + t * 16 + (lane & 15)) * 128);
                LDSM4(ah[t], stgA  + ro + akoff);
                LDSM4(al[t], stgAl + ro + akoff);
            }
            const unsigned bkoff = ((unsigned)((ks * 2 + ((lane >> 3) & 1)) ^ (lane & 7))) << 4;
#pragma unroll
            for (int p = 0; p < 4; p++) {
                const unsigned ro = (unsigned)((wn * 64 + p * 16 + (lane & 7) + ((lane & 16) >> 1)) * 128);
                unsigned r[4];
                LDSM4(r, stgB + ro + bkoff);
                bb[2*p][0] = r[0]; bb[2*p][1] = r[1];
                bb[2*p+1][0] = r[2]; bb[2*p+1][1] = r[3];
            }
#pragma unroll
            for (int t = 0; t < 4; t++)
#pragma unroll
                for (int u = 0; u < 8; u++) {
                    MMA16816H(acc[t][u], ah[t], bb[u]);
                    MMA16816H(acc[t][u], al[t], bb[u]);
                }
        }
        __syncthreads();
    }

#pragma unroll
    for (int t = 0; t < 4; t++) {
        const int row = m0 + wm * 64 + t * 16 + (lane >> 2);
#pragma unroll
        for (int u = 0; u < 8; u++) {
            const int col = n0 + wn * 64 + u * 8 + (lane & 3) * 2;
            if (col < N) {
                *(float2*)(C + (size_t)row * ldC + col)       = make_float2(acc[t][u][0], acc[t][u][1]);
                *(float2*)(C + (size_t)(row + 8) * ldC + col) = make_float2(acc[t][u][2], acc[t][u][3]);
            }
        }
    }
}

// =====================================================================
// fp32 -> (fp16 hi, fp16 lo) split conversion
// =====================================================================
__global__ void __launch_bounds__(256) cvt_pair(const float* __restrict__ src,
                                                __half* __restrict__ h,
                                                __half* __restrict__ l, int n4)
{
    const int i = blockIdx.x * 256 + threadIdx.x;
    if (i >= n4) return;
    const float4 v = ((const float4*)src)[i];
    __half h0 = __float2half_rn(v.x), h1 = __float2half_rn(v.y),
           h2 = __float2half_rn(v.z), h3 = __float2half_rn(v.w);
    __half l0 = __float2half_rn(v.x - __half2float(h0));
    __half l1 = __float2half_rn(v.y - __half2float(h1));
    __half l2 = __float2half_rn(v.z - __half2float(h2));
    __half l3 = __float2half_rn(v.w - __half2float(h3));
    ushort4 hv = make_ushort4(__half_as_ushort(h0), __half_as_ushort(h1),
                              __half_as_ushort(h2), __half_as_ushort(h3));
    ushort4 lv = make_ushort4(__half_as_ushort(l0), __half_as_ushort(l1),
                              __half_as_ushort(l2), __half_as_ushort(l3));
    ((ushort4*)h)[i] = hv;
    ((ushort4*)l)[i] = lv;
}

// =====================================================================
// Exact fp32 dt projection (smem-tiled mini-GEMM) — unchanged from R13
// =====================================================================
#define DTP_RPC 64
#define SQ_LD   36
#define SW_LD   34

__global__ void __launch_bounds__(256) dtproj_kernel(const float* __restrict__ q,
                                                     const float* __restrict__ w1)
{
    __shared__ float sq[DTP_RPC * SQ_LD];
    __shared__ float sW[32 * SW_LD];

    const int tid = threadIdx.x;
    const int r0  = blockIdx.x * DTP_RPC;
    const int rg  = tid >> 4;
    const int cp  = tid & 15;

    ull acc[4];
#pragma unroll
    for (int i = 0; i < 4; i++) acc[i] = 0ull;

    for (int k0 = 0; k0 < D_MODEL; k0 += 32) {
        __syncthreads();
        {
            const int row = tid >> 3;
            const int kk  = (tid & 7) * 4;
#pragma unroll
            for (int i = 0; i < 2; i++) {
                const int r = row + i * 32;
                float4 v = *(const float4*)(q + (size_t)(r0 + r) * D_MODEL + k0 + kk);
                *(float4*)(sq + r * SQ_LD + kk) = v;
            }
        }
        {
            const int c  = tid >> 3;
            const int kk = (tid & 7) * 4;
            float4 v = *(const float4*)(w1 + ((size_t)N_MAIN + c) * D_MODEL + k0 + kk);
            sW[(kk + 0) * SW_LD + c] = v.x;
            sW[(kk + 1) * SW_LD + c] = v.y;
            sW[(kk + 2) * SW_LD + c] = v.z;
            sW[(kk + 3) * SW_LD + c] = v.w;
        }
        __syncthreads();

#pragma unroll 8
        for (int k = 0; k < 32; k += 4) {
            ull wq[4];
#pragma unroll
            for (int j = 0; j < 4; j++)
                wq[j] = *(const ull*)(sW + (k + j) * SW_LD + cp * 2);
#pragma unroll
            for (int i = 0; i < 4; i++) {
                const float4 qv = *(const float4*)(sq + (rg * 4 + i) * SQ_LD + k);
                fma2(acc[i], pack2(qv.x, qv.x), wq[0]);
                fma2(acc[i], pack2(qv.y, qv.y), wq[1]);
                fma2(acc[i], pack2(qv.z, qv.z), wq[2]);
                fma2(acc[i], pack2(qv.w, qv.w), wq[3]);
            }
        }
    }

#pragma unroll
    for (int i = 0; i < 4; i++) {
        float lo, hi; unpack2(acc[i], lo, hi);
        const int row = r0 + rg * 4 + i;
        *(float2*)(g_dtraw + (size_t)row * NHEADS + cp * 2) = make_float2(lo, hi);
    }
}

// =====================================================================
// Depthwise causal conv (width 4) + SiLU + fp16 hi/lo emission
// =====================================================================
__global__ void __launch_bounds__(256) conv_silu_kernel(const float* __restrict__ conv_w,
                                                        const float* __restrict__ conv_b)
{
    const int c  = blockIdx.x * 256 + threadIdx.x;
    const int l0 = blockIdx.y * 128;
    const int b  = blockIdx.z;

    const float w0 = conv_w[c*4+0], w1 = conv_w[c*4+1],
                w2 = conv_w[c*4+2], w3 = conv_w[c*4+3];
    const float bias = conv_b[c];

    const float* src = g_zxb + (size_t)(b*SEQ) * D_IN_PROJ + D_INNER + c;
    float*       dst = g_xbc + (size_t)(b*SEQ) * CONV_DIM + c;
    __half*      dsh = g_cv_h + (size_t)(b*SEQ) * CONV_DIM + c;
    __half*      dsl = g_cv_l + (size_t)(b*SEQ) * CONV_DIM + c;

    float xm3 = (l0-3 >= 0) ? src[(size_t)(l0-3) * D_IN_PROJ] : 0.f;
    float xm2 = (l0-2 >= 0) ? src[(size_t)(l0-2) * D_IN_PROJ] : 0.f;
    float xm1 = (l0-1 >= 0) ? src[(size_t)(l0-1) * D_IN_PROJ] : 0.f;

    for (int l = l0; l < l0 + 128; l++) {
        const float xc = src[(size_t)l * D_IN_PROJ];
        float v = bias + w0*xm3 + w1*xm2 + w2*xm1 + w3*xc;
        v = v / (1.f + expf(-v));
        dst[(size_t)l * CONV_DIM] = v;
        const __half hv = __float2half_rn(v);
        dsh[(size_t)l * CONV_DIM] = hv;
        dsl[(size_t)l * CONV_DIM] = __float2half_rn(v - __half2float(hv));
        xm3 = xm2; xm2 = xm1; xm1 = xc;
    }
}

// =====================================================================
// dt = softplus(dtraw + dt_bias); la = A*dt
// =====================================================================
__global__ void __launch_bounds__(256) dt_kernel(const float* __restrict__ dt_bias,
                                                 const float* __restrict__ A_log)
{
    const int idx = blockIdx.x * 256 + threadIdx.x;
    if (idx >= NBH*SEQ) return;
    const int l = idx & (SEQ-1);
    const int h = (idx >> 11) & (NHEADS-1);
    const int b = idx >> 16;
    const float raw = g_dtraw[(size_t)(b*SEQ + l) * NHEADS + h] + dt_bias[h];
    const float sp = (raw > 20.f) ? raw : log1pf(expf(raw));
    const float Ahv = -expf(A_log[h]);
    g_dt[idx] = sp;
    g_la[idx] = Ahv * sp;
}

// =====================================================================
// SSD phase 1: per-chunk local state (fp32, unchanged)
// =====================================================================
#define SSDA_SMEM ((128*PR + 128*PX + 384) * 4)

__global__ void __launch_bounds__(256, 2) ssd_state_kernel()
{
    extern __shared__ float sma[];
    float* sB  = sma;
    float* sVW = sB + 128*PR;
    float* sCS = sVW + 128*PX;
    float* sDT = sCS + 128;
    float* sLA = sDT + 128;

    const int ck = blockIdx.x, bh = blockIdx.y;
    const int b  = bh >> 5, hh = bh & 31;
    const int tid = threadIdx.x;
    const size_t rbase = (size_t)(b*SEQ + ck*LCH);

#pragma unroll
    for (int i = 0; i < 16; i++) {
        int idx = i*256 + tid; int t = idx >> 5, f4 = idx & 31;
        cp16(smem_u32(sB + t*PR + f4*4),
             g_xbc + (rbase + t)*CONV_DIM + D_INNER + f4*4);
    }
#pragma unroll
    for (int i = 0; i < 8; i++) {
        int idx = i*256 + tid; int t = idx >> 4, f4 = idx & 15;
        cp16(smem_u32(sVW + t*PX + f4*4),
             g_xbc + (rbase + t)*CONV_DIM + hh*HEADDIM + f4*4);
    }
    if (tid < 128) {
        sDT[tid] = g_dt[(size_t)bh*SEQ + ck*LCH + tid];
        sLA[tid] = g_la[(size_t)bh*SEQ + ck*LCH + tid];
    }
    cp_commit(); cp_wait<0>();
    __syncthreads();
    if (tid == 0) {
        float c = 0.f;
        for (int s = 0; s < 128; s++) { c += sLA[s]; sCS[s] = c; }
    }
    __syncthreads();
    const float csL = sCS[127];
    if (tid < 128) {
        const float w = __expf(csL - sCS[tid]) * sDT[tid];
        float* row = sVW + tid*PX;
#pragma unroll
        for (int p = 0; p < 64; p += 4) {
            float4 v = *(float4*)(row + p);
            v.x *= w; v.y *= w; v.z *= w; v.w *= w;
            *(float4*)(row + p) = v;
        }
    }
    if (tid == 0) g_cum[bh*NCHUNK + ck] = __expf(csL);
    __syncthreads();

    const int pg = tid >> 4;
    const int ng = tid & 15;

    ull Sp[4][4];
#pragma unroll
    for (int i = 0; i < 4; i++)
#pragma unroll
        for (int q = 0; q < 4; q++) Sp[i][q] = 0ull;

#pragma unroll 4
    for (int s = 0; s < 128; s++) {
        const float4 v4  = *(const float4*)(sVW + s*PX + pg*4);
        const float4 b40 = *(const float4*)(sB + s*PR + ng*8);
        const float4 b41 = *(const float4*)(sB + s*PR + ng*8 + 4);
        ull bp[4] = { pack2(b40.x, b40.y), pack2(b40.z, b40.w),
                      pack2(b41.x, b41.y), pack2(b41.z, b41.w) };
#pragma unroll
        for (int i = 0; i < 4; i++) {
            const float vv = COMP(v4, i);
            const ull vc = pack2(vv, vv);
#pragma unroll
            for (int q = 0; q < 4; q++) fma2(Sp[i][q], vc, bp[q]);
        }
    }

    float* dst = g_st + (size_t)(bh*NCHUNK + ck)*STATE_SZ;
#pragma unroll
    for (int i = 0; i < 4; i++) {
        const int p = pg*4 + i;
        float o[8];
#pragma unroll
        for (int q = 0; q < 4; q++) unpack2(Sp[i][q], o[q*2], o[q*2+1]);
        *(float4*)(dst + p*D_STATE + ng*8)     = make_float4(o[0], o[1], o[2], o[3]);
        *(float4*)(dst + p*D_STATE + ng*8 + 4) = make_float4(o[4], o[5], o[6], o[7]);
    }
}

// =====================================================================
// SSD phase 2: combine across chunks; emit h_init as fp16 hi/lo.
// thread: p = tid>>2, n0 = (tid&3)*32
// =====================================================================
__global__ void __launch_bounds__(256) chunk_combine_kernel()
{
    const int bh  = blockIdx.x;
    const int tid = threadIdx.x;
    const size_t off = (size_t)tid * 32;
    const int p  = tid >> 2;
    const int n0 = (tid & 3) * 32;

    float4 h[8];
#pragma unroll
    for (int i = 0; i < 8; i++) h[i] = make_float4(0.f, 0.f, 0.f, 0.f);

    for (int ck = 0; ck < NCHUNK; ck++) {
        const size_t hb = (size_t)(bh * NCHUNK + ck) * STATE_SZ + (size_t)p * 128 + n0;
#pragma unroll
        for (int i = 0; i < 8; i++) {
            const float4 v = h[i];
            __half h0 = __float2half_rn(v.x), h1 = __float2half_rn(v.y),
                   h2 = __float2half_rn(v.z), h3 = __float2half_rn(v.w);
            ushort4 hv = make_ushort4(__half_as_ushort(h0), __half_as_ushort(h1),
                                      __half_as_ushort(h2), __half_as_ushort(h3));
            ushort4 lv = make_ushort4(
                __half_as_ushort(__float2half_rn(v.x - __half2float(h0))),
                __half_as_ushort(__float2half_rn(v.y - __half2float(h1))),
                __half_as_ushort(__float2half_rn(v.z - __half2float(h2))),
                __half_as_ushort(__float2half_rn(v.w - __half2float(h3))));
            *(ushort4*)(g_h16h + hb + i*4) = hv;
            *(ushort4*)(g_h16l + hb + i*4) = lv;
        }
        if (ck < NCHUNK - 1) {
            const float a = g_cum[bh * NCHUNK + ck];
            const float4* s = (const float4*)(g_st + (size_t)(bh * NCHUNK + ck) * STATE_SZ + off);
#pragma unroll
            for (int i = 0; i < 8; i++) {
                float4 sv = s[i];
                h[i].x = a * h[i].x + sv.x;
                h[i].y = a * h[i].y + sv.y;
                h[i].z = a * h[i].z + sv.z;
                h[i].w = a * h[i].w + sv.w;
            }
        }
    }
}

// =====================================================================
// SSD phase 3 (tensor cores):
//   G = C.B^T, Y2 = C.h^T (fused K=n loop), mask/weight G -> M (fp16 2-term),
//   Y = M.x + diag(exp(cs)).Y2 + D*x.
// All fp16 operands 2-term (hi/lo); 3 cross-term MMA passes each.
// 8 warps: wm = wid>>2 (t rows 64 each), wn = wid&3.
// G warp tile 64t x 32s; Y warp tile 64t x 16p.
// SMEM (200192 B):
//  0 sCh |32768 sCl |65536 sBh->sMh |98304 sBl->sMl |131072 shh->sxTh
//  |147456 shl->sxTl |163840 sXf(f32,128x68) |198656 sCS |199168 sDT |199680 sLA
// =====================================================================
#define SSDT_SMEM 200192

__global__ void __launch_bounds__(256, 1) ssd_out_tc(const float* __restrict__ Dvec)
{
    extern __shared__ __align__(1024) char smc[];
    const unsigned base = smem_u32(smc);
    const unsigned uCh = base;
    const unsigned uCl = base + 32768;
    const unsigned uBh = base + 65536;     // later M hi
    const unsigned uBl = base + 98304;     // later M lo
    const unsigned uhh = base + 131072;    // later xT hi
    const unsigned uhl = base + 147456;    // later xT lo
    float* sXf = (float*)(smc + 163840);
    float* sCS = (float*)(smc + 198656);
    float* sDT = (float*)(smc + 199168);
    float* sLA = (float*)(smc + 199680);

    const int ck = blockIdx.x, bh = blockIdx.y;
    const int b  = bh >> 5, hh = bh & 31;
    const int tid  = threadIdx.x;
    const int lane = tid & 31;
    const int wid  = tid >> 5;
    const int wm   = wid >> 2;       // 0..1
    const int wn   = wid & 3;        // 0..3
    const size_t rbase = (size_t)(b*SEQ + ck*LCH);

    // ---- async loads (fp16 pre-split operands + fp32 x) ----
#pragma unroll
    for (int i = 0; i < 8; i++) {            // C: 2048 16B-chunks
        int idx = i*256 + tid; int r = idx >> 4, ch = idx & 15;
        const unsigned off = (unsigned)(r*256) + ((unsigned)(ch ^ (r & 7)) << 4);
        const size_t g = (rbase + r)*CONV_DIM + 2176 + ch*8;
        cp16(uCh + off, g_cv_h + g);
        cp16(uCl + off, g_cv_l + g);
    }
#pragma unroll
    for (int i = 0; i < 8; i++) {            // B
        int idx = i*256 + tid; int r = idx >> 4, ch = idx & 15;
        const unsigned off = (unsigned)(r*256) + ((unsigned)(ch ^ (r & 7)) << 4);
        const size_t g = (rbase + r)*CONV_DIM + 2048 + ch*8;
        cp16(uBh + off, g_cv_h + g);
        cp16(uBl + off, g_cv_l + g);
    }
    {
        const size_t hb = (size_t)(bh*NCHUNK + ck) * STATE_SZ;
#pragma unroll
        for (int i = 0; i < 4; i++) {        // h: 1024 chunks
            int idx = i*256 + tid; int r = idx >> 4, ch = idx & 15;
            const unsigned off = (unsigned)(r*256) + ((unsigned)(ch ^ (r & 7)) << 4);
            cp16(uhh + off, g_h16h + hb + r*128 + ch*8);
            cp16(uhl + off, g_h16l + hb + r*128 + ch*8);
        }
    }
#pragma unroll
    for (int i = 0; i < 8; i++) {            // x fp32
        int idx = i*256 + tid; int t = idx >> 4, f4 = idx & 15;
        cp16(smem_u32(sXf + t*PX + f4*4),
             g_xbc + (rbase + t)*CONV_DIM + hh*HEADDIM + f4*4);
    }
    if (tid < 128) {
        sDT[tid] = g_dt[(size_t)bh*SEQ + ck*LCH + tid];
        sLA[tid] = g_la[(size_t)bh*SEQ + ck*LCH + tid];
    }
    cp_commit(); cp_wait<0>();
    __syncthreads();
    if (tid == 0) {
        float c = 0.f;
        for (int s = 0; s < 128; s++) { c += sLA[s]; sCS[s] = c; }
    }
    __syncthreads();

    // ---- fused G + Y2 K-loop (K = n = 128, 8 k16 steps) ----
    float Gacc[4][4][4];
    float Yacc[4][2][4];
#pragma unroll
    for (int mt = 0; mt < 4; mt++) {
#pragma unroll
        for (int u = 0; u < 4; u++)
#pragma unroll
            for (int v = 0; v < 4; v++) Gacc[mt][u][v] = 0.f;
#pragma unroll
        for (int u = 0; u < 2; u++)
#pragma unroll
            for (int v = 0; v < 4; v++) Yacc[mt][u][v] = 0.f;
    }

#pragma unroll
    for (int ks = 0; ks < 8; ks++) {
        unsigned ah[4][4], al[4][4];
        const unsigned akoff = ((unsigned)((ks*2 + (lane >> 4)) ^ (lane & 7))) << 4;
#pragma unroll
        for (int mt = 0; mt < 4; mt++) {
            const unsigned ro = (unsigned)((wm*64 + mt*16 + (lane & 15)) * 256);
            LDSM4(ah[mt], uCh + ro + akoff);
            LDSM4(al[mt], uCl + ro + akoff);
        }
        const unsigned bkoff = ((unsigned)((ks*2 + ((lane >> 3) & 1)) ^ (lane & 7))) << 4;
        unsigned bGh[4][2], bGl[4][2], bYh[2][2], bYl[2][2];
#pragma unroll
        for (int g = 0; g < 2; g++) {
            const unsigned ro = (unsigned)((wn*32 + g*16 + (lane & 7) + ((lane & 16) >> 1)) * 256);
            unsigned r[4];
            LDSM4(r, uBh + ro + bkoff);
            bGh[2*g][0] = r[0]; bGh[2*g][1] = r[1];
            bGh[2*g+1][0] = r[2]; bGh[2*g+1][1] = r[3];
            LDSM4(r, uBl + ro + bkoff);
            bGl[2*g][0] = r[0]; bGl[2*g][1] = r[1];
            bGl[2*g+1][0] = r[2]; bGl[2*g+1][1] = r[3];
        }
        {
            const unsigned ro = (unsigned)((wn*16 + (lane & 7) + ((lane & 16) >> 1)) * 256);
            unsigned r[4];
            LDSM4(r, uhh + ro + bkoff);
            bYh[0][0] = r[0]; bYh[0][1] = r[1];
            bYh[1][0] = r[2]; bYh[1][1] = r[3];
            LDSM4(r, uhl + ro + bkoff);
            bYl[0][0] = r[0]; bYl[0][1] = r[1];
            bYl[1][0] = r[2]; bYl[1][1] = r[3];
        }
#pragma unroll
        for (int mt = 0; mt < 4; mt++) {
#pragma unroll
            for (int u = 0; u < 4; u++) {
                MMA16816H(Gacc[mt][u], ah[mt], bGh[u]);
                MMA16816H(Gacc[mt][u], al[mt], bGh[u]);
                MMA16816H(Gacc[mt][u], ah[mt], bGl[u]);
            }
#pragma unroll
            for (int u = 0; u < 2; u++) {
                MMA16816H(Yacc[mt][u], ah[mt], bYh[u]);
                MMA16816H(Yacc[mt][u], al[mt], bYh[u]);
                MMA16816H(Yacc[mt][u], ah[mt], bYl[u]);
            }
        }
    }

    // scale Y2 by exp(cs_t)
#pragma unroll
    for (int mt = 0; mt < 4; mt++) {
        const int t0 = wm*64 + mt*16 + (lane >> 2);
        const float e0 = __expf(sCS[t0]);
        const float e1 = __expf(sCS[t0 + 8]);
#pragma unroll
        for (int u = 0; u < 2; u++) {
            Yacc[mt][u][0] *= e0; Yacc[mt][u][1] *= e0;
            Yacc[mt][u][2] *= e1; Yacc[mt][u][3] *= e1;
        }
    }

    __syncthreads();   // all warps done reading B / h smem

    // ---- mask + weight G -> M (fp16 hi/lo into uBh/uBl) ----
#pragma unroll
    for (int mt = 0; mt < 4; mt++) {
        const int t0 = wm*64 + mt*16 + (lane >> 2);
        const int t1 = t0 + 8;
        const float cs0 = sCS[t0], cs1 = sCS[t1];
#pragma unroll
        for (int u = 0; u < 4; u++) {
            const int s0 = wn*32 + u*8 + (lane & 3)*2;
            const int s1 = s0 + 1;
            const float w00 = (s0 <= t0) ? __expf(cs0 - sCS[s0]) * sDT[s0] : 0.f;
            const float w01 = (s1 <= t0) ? __expf(cs0 - sCS[s1]) * sDT[s1] : 0.f;
            const float w10 = (s0 <= t1) ? __expf(cs1 - sCS[s0]) * sDT[s0] : 0.f;
            const float w11 = (s1 <= t1) ? __expf(cs1 - sCS[s1]) * sDT[s1] : 0.f;
            const float m00 = Gacc[mt][u][0] * w00;
            const float m01 = Gacc[mt][u][1] * w01;
            const float m10 = Gacc[mt][u][2] * w10;
            const float m11 = Gacc[mt][u][3] * w11;
            const unsigned cOff = ((unsigned)((s0 >> 3) ^ (t0 & 7)) << 4) + (unsigned)((s0 & 7) * 2);
            const unsigned cOff1 = ((unsigned)((s0 >> 3) ^ (t1 & 7)) << 4) + (unsigned)((s0 & 7) * 2);
            const __half h00 = __float2half_rn(m00), h01 = __float2half_rn(m01);
            const __half h10 = __float2half_rn(m10), h11 = __float2half_rn(m11);
            unsigned pk;
            pk = (unsigned)__half_as_ushort(h00) | ((unsigned)__half_as_ushort(h01) << 16);
            *(unsigned*)(smc + 65536 + t0*256 + cOff) = pk;
            pk = (unsigned)__half_as_ushort(__float2half_rn(m00 - __half2float(h00)))
               | ((unsigned)__half_as_ushort(__float2half_rn(m01 - __half2float(h01))) << 16);
            *(unsigned*)(smc + 98304 + t0*256 + cOff) = pk;
            pk = (unsigned)__half_as_ushort(h10) | ((unsigned)__half_as_ushort(h11) << 16);
            *(unsigned*)(smc + 65536 + t1*256 + cOff1) = pk;
            pk = (unsigned)__half_as_ushort(__float2half_rn(m10 - __half2float(h10)))
               | ((unsigned)__half_as_ushort(__float2half_rn(m11 - __half2float(h11))) << 16);
            *(unsigned*)(smc + 98304 + t1*256 + cOff1) = pk;
        }
    }

    // ---- transpose x (fp32) -> xT fp16 hi/lo into uhh/uhl region ----
#pragma unroll
    for (int i = 0; i < 32; i++) {
        const int e = i*256 + tid;
        const int s = e >> 6, p = e & 63;
        const float xv = sXf[s*PX + p];
        const __half hv = __float2half_rn(xv);
        const __half lv = __float2half_rn(xv - __half2float(hv));
        const unsigned off = (unsigned)(p*256) + ((unsigned)((s >> 3) ^ (p & 7)) << 4)
                           + (unsigned)((s & 7) * 2);
        *(unsigned short*)(smc + 131072 + off) = __half_as_ushort(hv);
        *(unsigned short*)(smc + 147456 + off) = __half_as_ushort(lv);
    }
    __syncthreads();

    // ---- Y1: Y += M . x^T   (K = s = 128) ----
#pragma unroll
    for (int ks = 0; ks < 8; ks++) {
        unsigned mh[4][4], ml[4][4], bXh[2][2], bXl[2][2];
        const unsigned akoff = ((unsigned)((ks*2 + (lane >> 4)) ^ (lane & 7))) << 4;
#pragma unroll
        for (int mt = 0; mt < 4; mt++) {
            const unsigned ro = (unsigned)((wm*64 + mt*16 + (lane & 15)) * 256);
            LDSM4(mh[mt], uBh + ro + akoff);
            LDSM4(ml[mt], uBl + ro + akoff);
        }
        const unsigned bkoff = ((unsigned)((ks*2 + ((lane >> 3) & 1)) ^ (lane & 7))) << 4;
        {
            const unsigned ro = (unsigned)((wn*16 + (lane & 7) + ((lane & 16) >> 1)) * 256);
            unsigned r[4];
            LDSM4(r, uhh + ro + bkoff);
            bXh[0][0] = r[0]; bXh[0][1] = r[1];
            bXh[1][0] = r[2]; bXh[1][1] = r[3];
            LDSM4(r, uhl + ro + bkoff);
            bXl[0][0] = r[0]; bXl[0][1] = r[1];
            bXl[1][0] = r[2]; bXl[1][1] = r[3];
        }
#pragma unroll
        for (int mt = 0; mt < 4; mt++)
#pragma unroll
            for (int u = 0; u < 2; u++) {
                MMA16816H(Yacc[mt][u], mh[mt], bXh[u]);
                MMA16816H(Yacc[mt][u], ml[mt], bXh[u]);
                MMA16816H(Yacc[mt][u], mh[mt], bXl[u]);
            }
    }

    // ---- epilogue: + D*x, write y ----
    const float Dv = Dvec[hh];
#pragma unroll
    for (int mt = 0; mt < 4; mt++) {
        const int t0 = wm*64 + mt*16 + (lane >> 2);
        const int t1 = t0 + 8;
#pragma unroll
        for (int u = 0; u < 2; u++) {
            const int p0 = wn*16 + u*8 + (lane & 3)*2;
            float2 o0, o1;
            o0.x = Yacc[mt][u][0] + Dv * sXf[t0*PX + p0];
            o0.y = Yacc[mt][u][1] + Dv * sXf[t0*PX + p0 + 1];
            o1.x = Yacc[mt][u][2] + Dv * sXf[t1*PX + p0];
            o1.y = Yacc[mt][u][3] + Dv * sXf[t1*PX + p0 + 1];
            *(float2*)(g_yb + ((rbase + t0) * NHEADS + hh) * HEADDIM + p0) = o0;
            *(float2*)(g_yb + ((rbase + t1) * NHEADS + hh) * HEADDIM + p0) = o1;
        }
    }
}

// =====================================================================
// y = yb * silu(z); rmsnorm; write fp16 hi/lo split
// =====================================================================
__global__ void __launch_bounds__(256) gate_norm_kernel(const float* __restrict__ norm_w)
{
    const int row = blockIdx.x;
    const int tid = threadIdx.x;
    const float* yb = g_yb + (size_t)row * D_INNER;
    const float* zr = g_zxb + (size_t)row * D_IN_PROJ;

    float4 v[2];
    float ss = 0.f;
#pragma unroll
    for (int j = 0; j < 2; j++) {
        const int idx = tid + j*256;
        const float4 z4 = ((const float4*)zr)[idx];
        const float4 y4 = ((const float4*)yb)[idx];
        float4 val;
        val.x = y4.x * (z4.x / (1.f + expf(-z4.x)));
        val.y = y4.y * (z4.y / (1.f + expf(-z4.y)));
        val.z = y4.z * (z4.z / (1.f + expf(-z4.z)));
        val.w = y4.w * (z4.w / (1.f + expf(-z4.w)));
        v[j] = val;
        ss += val.x*val.x + val.y*val.y + val.z*val.z + val.w*val.w;
    }
#pragma unroll
    for (int o = 16; o > 0; o >>= 1) ss += __shfl_xor_sync(0xffffffffu, ss, o);

    __shared__ float red[8];
    __shared__ float sscale;
    if ((tid & 31) == 0) red[tid >> 5] = ss;
    __syncthreads();
    if (tid == 0) {
        float tot = 0.f;
#pragma unroll
        for (int i = 0; i < 8; i++) tot += red[i];
        sscale = rsqrtf(tot / (float)D_INNER + EPSV);
    }
    __syncthreads();
    const float scale = sscale;

    __half* oh = g_ynh + (size_t)row * D_INNER;
    __half* ol = g_ynl + (size_t)row * D_INNER;
#pragma unroll
    for (int j = 0; j < 2; j++) {
        const int idx = tid + j*256;
        const float4 w4 = ((const float4*)norm_w)[idx];
        float y[4] = { v[j].x * scale * w4.x, v[j].y * scale * w4.y,
                       v[j].z * scale * w4.z, v[j].w * scale * w4.w };
        ushort4 hv, lv;
        __half h0 = __float2half_rn(y[0]); hv.x = __half_as_ushort(h0);
        __half h1 = __float2half_rn(y[1]); hv.y = __half_as_ushort(h1);
        __half h2 = __float2half_rn(y[2]); hv.z = __half_as_ushort(h2);
        __half h3 = __float2half_rn(y[3]); hv.w = __half_as_ushort(h3);
        lv.x = __half_as_ushort(__float2half_rn(y[0] - __half2float(h0)));
        lv.y = __half_as_ushort(__float2half_rn(y[1] - __half2float(h1)));
        lv.z = __half_as_ushort(__float2half_rn(y[2] - __half2float(h2)));
        lv.w = __half_as_ushort(__float2half_rn(y[3] - __half2float(h3)));
        ((ushort4*)oh)[idx] = hv;
        ((ushort4*)ol)[idx] = lv;
    }
}

// =====================================================================
// Launch
// inputs: 0 query, 1 key, 2 value, 3 in_proj_w, 4 conv_w, 5 conv_b,
//         6 dt_bias, 7 A_log, 8 D, 9 norm_w, 10 out_proj_w
// =====================================================================
extern "C" void kernel_launch(void* const* d_in, const int* in_sizes, int n_in,
                              void* d_out, int out_size)
{
    const float* q          = (const float*)d_in[0];
    const float* in_proj_w  = (const float*)d_in[3];
    const float* conv_w     = (const float*)d_in[4];
    const float* conv_b     = (const float*)d_in[5];
    const float* dt_bias    = (const float*)d_in[6];
    const float* A_log      = (const float*)d_in[7];
    const float* Dvec       = (const float*)d_in[8];
    const float* norm_w     = (const float*)d_in[9];
    const float* out_proj_w = (const float*)d_in[10];
    float* out              = (float*)d_out;

    float* zxb; cudaGetSymbolAddress((void**)&zxb, g_zxb);
    __half *qh, *ql, *w1h, *w1l, *ynh, *ynl, *w2h, *w2l;
    cudaGetSymbolAddress((void**)&qh,  g_qh);
    cudaGetSymbolAddress((void**)&ql,  g_ql);
    cudaGetSymbolAddress((void**)&w1h, g_w1h);
    cudaGetSymbolAddress((void**)&w1l, g_w1l);
    cudaGetSymbolAddress((void**)&ynh, g_ynh);
    cudaGetSymbolAddress((void**)&ynl, g_ynl);
    cudaGetSymbolAddress((void**)&w2h, g_w2h);
    cudaGetSymbolAddress((void**)&w2l, g_w2l);

    cudaFuncSetAttribute(gemm_mma, cudaFuncAttributeMaxDynamicSharedMemorySize, GEMM_SMEM);
    cudaFuncSetAttribute(ssd_state_kernel, cudaFuncAttributeMaxDynamicSharedMemorySize, SSDA_SMEM);
    cudaFuncSetAttribute(ssd_out_tc, cudaFuncAttributeMaxDynamicSharedMemorySize, SSDT_SMEM);

    // 0) split-convert GEMM operands (fp16 hi/lo)
    {
        const int nq = ROWS * D_MODEL / 4;
        cvt_pair<<<(nq + 255)/256, 256>>>(q, qh, ql, nq);
        const int nw1 = N_MAIN * D_MODEL / 4;
        cvt_pair<<<(nw1 + 255)/256, 256>>>(in_proj_w, w1h, w1l, nw1);
        const int nw2 = D_MODEL * D_INNER / 4;
        cvt_pair<<<(nw2 + 255)/256, 256>>>(out_proj_w, w2h, w2l, nw2);
    }

    // 0b) exact fp32 dt projection
    dtproj_kernel<<<ROWS/DTP_RPC, 256>>>(q, in_proj_w);

    // 1) zxbcdt[:, :4352] = q @ in_proj_w[:4352]^T
    gemm_mma<<<dim3(N_MAIN/256, ROWS/128), 256, GEMM_SMEM>>>(
        qh, ql, w1h, zxb, ROWS, N_MAIN, D_MODEL, D_IN_PROJ);

    // 2) causal conv4 + SiLU (+ fp16 hi/lo emission)
    conv_silu_kernel<<<dim3(CONV_DIM/256, SEQ/128, BATCH), 256>>>(conv_w, conv_b);

    // 3) dt / la
    dt_kernel<<<(NBH*SEQ + 255)/256, 256>>>(dt_bias, A_log);

    // 4) SSD chunked scan: fp32 states, fp16-HMMA output phase
    ssd_state_kernel<<<dim3(NCHUNK, NBH), 256, SSDA_SMEM>>>();
    chunk_combine_kernel<<<NBH, 256>>>();
    ssd_out_tc<<<dim3(NCHUNK, NBH), 256, SSDT_SMEM>>>(Dvec);

    // 5) gate + RMSNorm (emits fp16 hi/lo)
    gate_norm_kernel<<<ROWS, 256>>>(norm_w);

    // 6) out = yn @ out_proj_w^T
    gemm_mma<<<dim3(D_MODEL/256, ROWS/128), 256, GEMM_SMEM>>>(
        ynh, ynl, w2h, out, ROWS, D_MODEL, D_INNER, D_MODEL);
}